// round 4
// baseline (speedup 1.0000x reference)
#include <cuda_runtime.h>
#include <cstdint>
#include <math.h>

// Problem dims (fixed)
#define Bb 128
#define Tt 512
#define Hh 1024
#define BT (Bb*Tt)
#define RCg 64     // recurrence CTAs (each owns 16 output cols)

// -------- device-global scratch ------------------------------------------
__device__ float g_xp[(size_t)BT * Hh];    // 256 MB input projections [T][B][H]
__device__ float g_hr[(size_t)BT * Hh];    // 256 MB rounded+permuted h [B][T][H]
__device__ float g_h[2][Bb * Hh];          // h double buffer (rounded+permuted)
__device__ float g_embr[1024 * 1024];      // rounded+permuted embed table
__device__ float g_Wxr[1024 * 1024];       // rounded+permuted Wx
__device__ float g_Wor[1024 * 1024];       // rounded+permuted Wo
__device__ unsigned int g_bar;

// -------- helpers --------------------------------------------------------
__device__ __forceinline__ uint32_t f2t(float x) {
    uint32_t u; asm("cvt.rna.tf32.f32 %0, %1;" : "=r"(u) : "f"(x));
    return u;
}
__device__ __forceinline__ float rndt(float x) { return __uint_as_float(f2t(x)); }
// k-pair interleave within 8-blocks: (j, j+4) -> positions (2j, 2j+1)
__device__ __forceinline__ int pig(int k) {
    int j = k & 7;
    return (k & ~7) | ((j < 4) ? (2 * j) : (2 * (j - 4) + 1));
}
__device__ __forceinline__ void cp16(float* s, const float* g) {
    uint32_t sa = (uint32_t)__cvta_generic_to_shared(s);
    asm volatile("cp.async.cg.shared.global [%0], [%1], 16;\n" :: "r"(sa), "l"(g));
}
__device__ __forceinline__ void cp_commit() { asm volatile("cp.async.commit_group;\n"); }
template<int N> __device__ __forceinline__ void cp_wait() {
    asm volatile("cp.async.wait_group %0;\n" :: "n"(N));
}
__device__ __forceinline__ void mma8(float* c, const uint32_t* a, const uint32_t* b) {
    asm volatile(
        "mma.sync.aligned.m16n8k8.row.col.f32.tf32.tf32.f32 "
        "{%0,%1,%2,%3},{%4,%5,%6,%7},{%8,%9},{%0,%1,%2,%3};"
        : "+f"(c[0]), "+f"(c[1]), "+f"(c[2]), "+f"(c[3])
        : "r"(a[0]), "r"(a[1]), "r"(a[2]), "r"(a[3]), "r"(b[0]), "r"(b[1]));
}

// -------- prologue: round+permute embed, Wx, Wo --------------------------
__global__ void prep_k(const float* __restrict__ e, const float* __restrict__ wx,
                       const float* __restrict__ wo) {
    int st = gridDim.x * blockDim.x;
    for (int i = blockIdx.x * blockDim.x + threadIdx.x; i < 1024 * 1024; i += st) {
        int r = i >> 10, k = i & 1023;
        int d = (r << 10) | pig(k);
        g_embr[d] = rndt(e[i]);
        g_Wxr[d]  = rndt(wx[i]);
        g_Wor[d]  = rndt(wo[i]);
    }
}

__global__ void init_k(const float* __restrict__ h0) {
    int i = blockIdx.x * blockDim.x + threadIdx.x;
    if (i == 0) g_bar = 0u;
    for (int j = i; j < Bb * Hh; j += gridDim.x * blockDim.x) {
        int r = j >> 10, k = j & 1023;
        g_h[0][(r << 10) | pig(k)] = rndt(h0[j]);
    }
}

// -------- phase GEMM: C[m][n] = sum_k A[m][k]*W[n][k] + bias[n] ----------
// Tile 128x64xK32, 256 threads = 8 warps (4M x 2N) of 32x32.
// 3-stage cp.async ring, prefetch depth 2, one __syncthreads per K-step.
#define PS 44     // smem row stride (floats)
#define ASZ 5632  // 128*44 per stage
#define BSZ 2816  // 64*44 per stage

__device__ __forceinline__ void stage(const float* const* rp, const float* __restrict__ W,
                                      int n0, int k0, float* As, float* Bs, int tid) {
    #pragma unroll
    for (int j = 0; j < 4; j++) {                 // A: 128 rows x 32 floats
        int c = j * 256 + tid; int r = c >> 3, o = c & 7;
        cp16(As + r * PS + o * 4, rp[r] + k0 + o * 4);
    }
    #pragma unroll
    for (int j = 0; j < 2; j++) {                 // B: 64 rows x 32 floats
        int c = j * 256 + tid; int r = c >> 3, o = c & 7;
        cp16(Bs + r * PS + o * 4, W + (size_t)(n0 + r) * 1024 + k0 + o * 4);
    }
}

template<bool GATHER>
__global__ __launch_bounds__(256, 2) void gemm_k(const float* __restrict__ Ab,
                                                 const int* __restrict__ tok,
                                                 const float* __restrict__ W,
                                                 const float* __restrict__ bias,
                                                 float* __restrict__ C) {
    extern __shared__ float sm[];
    float* As = sm;                         // 3 x 5632
    float* Bs = sm + 3 * ASZ;               // 3 x 2816
    const float** rp = (const float**)(sm + 3 * ASZ + 3 * BSZ);  // 128 ptrs

    const int tid = threadIdx.x;
    if (tid < 128) {
        if (GATHER) rp[tid] = Ab + (size_t)tok[tid * Tt + blockIdx.y] * 1024;
        else        rp[tid] = Ab + ((size_t)blockIdx.y * 128 + tid) * 1024;
    }
    __syncthreads();

    const int n0 = blockIdx.x * 64;
    const int lane = tid & 31, w = tid >> 5;
    const int g = lane >> 2, t4 = lane & 3;
    const int wm = (w >> 1) * 32, wn = (w & 1) * 32;

    float acc[2][4][4];
    #pragma unroll
    for (int a = 0; a < 2; a++)
        #pragma unroll
        for (int b = 0; b < 4; b++)
            #pragma unroll
            for (int c = 0; c < 4; c++) acc[a][b][c] = 0.f;

    stage(rp, W, n0, 0, As, Bs, tid);            cp_commit();
    stage(rp, W, n0, 32, As + ASZ, Bs + BSZ, tid); cp_commit();

    int buf = 0;
    for (int ks = 0; ks < 32; ks++) {
        if (ks < 30) cp_wait<1>(); else cp_wait<0>();
        __syncthreads();
        if (ks < 30) {
            int nb = buf;            // (ks+2)%3 == buf+... rotate below
            // next stage buffer = (ks+2)%3 ; since buf == ks%3, that's (buf+2)%3
            nb = buf + 2; if (nb >= 3) nb -= 3;
            stage(rp, W, n0, (ks + 2) * 32, As + nb * ASZ, Bs + nb * BSZ, tid);
            cp_commit();
        }

        const float* A_ = As + buf * ASZ;
        const float* B_ = Bs + buf * BSZ;
        #pragma unroll
        for (int kk = 0; kk < 32; kk += 8) {
            uint32_t a[2][4];
            #pragma unroll
            for (int mi = 0; mi < 2; mi++) {
                float2 p0 = *(const float2*)&A_[(wm + mi * 16 + g) * PS + kk + 2 * t4];
                float2 p1 = *(const float2*)&A_[(wm + mi * 16 + 8 + g) * PS + kk + 2 * t4];
                a[mi][0] = __float_as_uint(p0.x); a[mi][1] = __float_as_uint(p1.x);
                a[mi][2] = __float_as_uint(p0.y); a[mi][3] = __float_as_uint(p1.y);
            }
            #pragma unroll
            for (int ni = 0; ni < 4; ni++) {
                float2 q = *(const float2*)&B_[(wn + ni * 8 + g) * PS + kk + 2 * t4];
                uint32_t b[2] = { __float_as_uint(q.x), __float_as_uint(q.y) };
                mma8(acc[0][ni], a[0], b);
                mma8(acc[1][ni], a[1], b);
            }
        }
        buf++; if (buf >= 3) buf -= 3;
    }

    const int m0 = blockIdx.y * 128;
    #pragma unroll
    for (int ni = 0; ni < 4; ni++) {
        int nc = n0 + wn + ni * 8 + 2 * t4;
        float b0 = bias[nc], b1 = bias[nc + 1];
        #pragma unroll
        for (int mi = 0; mi < 2; mi++) {
            int r0 = m0 + wm + mi * 16 + g;
            *(float2*)&C[(size_t)r0 * 1024 + nc] =
                make_float2(acc[mi][ni][0] + b0, acc[mi][ni][1] + b1);
            *(float2*)&C[(size_t)(r0 + 8) * 1024 + nc] =
                make_float2(acc[mi][ni][2] + b0, acc[mi][ni][3] + b1);
        }
    }
}

// -------- persistent recurrence kernel -----------------------------------
// 64 CTAs x 512 thr (16 warps). CTA owns 16 output cols. Warp (mh,kw):
// M-half [64*mh,+64) x K-eighth [128*kw,+128). 4 warps/SMSP for latency
// cover. B (Wh slice) resident in smem; A (h) streamed L2->regs (__ldcg,
// depth-1 prefetch). 8 K-partials reduced in smem, tanh epilogue,
// grid barrier per step.
#define WS 1036   // Whs row stride
#define RS 20     // reduction row stride

__global__ __launch_bounds__(512, 1) void rnn_k(const float* __restrict__ Wh,
                                                const float* __restrict__ bh,
                                                float* __restrict__ h_e) {
    extern __shared__ float sm[];
    float* Whs = sm;                 // 16 x 1036 = 16576 floats
    float* Red = sm + 16576;         // 8 x 128 x 20 = 20480 floats

    const int tid = threadIdx.x, cta = blockIdx.x;

    // build rounded+permuted Wh slice in smem (once)
    for (int i = tid; i < 16 * 1024; i += 512) {
        int n = i >> 10, k = i & 1023;
        Whs[n * WS + pig(k)] = rndt(Wh[(size_t)(cta * 16 + n) * 1024 + k]);
    }
    __syncthreads();

    const int lane = tid & 31, w = tid >> 5;
    const int g = lane >> 2, t4 = lane & 3;
    const int mh = w >> 3, kw = w & 7;
    const int kb = kw * 128, mb = mh * 64;

    // epilogue mapping (first 256 threads): row em, cols [gc, gc+8)
    const int em = tid >> 1, ecol = (tid & 1) * 8;
    const int gc = cta * 16 + ecol;
    float4 bhA = make_float4(0.f, 0.f, 0.f, 0.f), bhB = bhA;
    if (tid < 256) {
        bhA = *(const float4*)&bh[gc];
        bhB = *(const float4*)&bh[gc + 4];
    }

    for (int t = 0; t < Tt; t++) {
        const float* hs = g_h[t & 1];
        float* hd = g_h[(t + 1) & 1];

        // prefetch xp for epilogue (latency hidden behind GEMM)
        float4 xpA, xpB;
        if (tid < 256) {
            xpA = *(const float4*)&g_xp[(size_t)(t * 128 + em) * 1024 + gc];
            xpB = *(const float4*)&g_xp[(size_t)(t * 128 + em) * 1024 + gc + 4];
        }

        float acc[4][2][4];
        #pragma unroll
        for (int a = 0; a < 4; a++)
            #pragma unroll
            for (int b = 0; b < 2; b++)
                #pragma unroll
                for (int c = 0; c < 4; c++) acc[a][b][c] = 0.f;

        float2 Ac[8], An[8];
        #pragma unroll
        for (int mf = 0; mf < 4; mf++) {
            Ac[2 * mf]     = __ldcg((const float2*)&hs[(mb + mf * 16 + g) * 1024 + kb + 2 * t4]);
            Ac[2 * mf + 1] = __ldcg((const float2*)&hs[(mb + mf * 16 + 8 + g) * 1024 + kb + 2 * t4]);
        }
        #pragma unroll
        for (int kk = 0; kk < 128; kk += 8) {
            if (kk < 120) {
                #pragma unroll
                for (int mf = 0; mf < 4; mf++) {
                    An[2 * mf]     = __ldcg((const float2*)&hs[(mb + mf * 16 + g) * 1024 + kb + kk + 8 + 2 * t4]);
                    An[2 * mf + 1] = __ldcg((const float2*)&hs[(mb + mf * 16 + 8 + g) * 1024 + kb + kk + 8 + 2 * t4]);
                }
            }
            #pragma unroll
            for (int nf = 0; nf < 2; nf++) {
                float2 q = *(const float2*)&Whs[(nf * 8 + g) * WS + kb + kk + 2 * t4];
                uint32_t b[2] = { __float_as_uint(q.x), __float_as_uint(q.y) };
                #pragma unroll
                for (int mf = 0; mf < 4; mf++) {
                    uint32_t a[4] = { __float_as_uint(Ac[2 * mf].x), __float_as_uint(Ac[2 * mf + 1].x),
                                      __float_as_uint(Ac[2 * mf].y), __float_as_uint(Ac[2 * mf + 1].y) };
                    mma8(acc[mf][nf], a, b);
                }
            }
            #pragma unroll
            for (int i = 0; i < 8; i++) Ac[i] = An[i];
        }

        // write warp-local K partials
        #pragma unroll
        for (int mf = 0; mf < 4; mf++)
            #pragma unroll
            for (int nf = 0; nf < 2; nf++) {
                int mr = mb + mf * 16 + g, n0l = nf * 8 + 2 * t4;
                *(float2*)&Red[(kw * 128 + mr) * RS + n0l] =
                    make_float2(acc[mf][nf][0], acc[mf][nf][1]);
                *(float2*)&Red[(kw * 128 + mr + 8) * RS + n0l] =
                    make_float2(acc[mf][nf][2], acc[mf][nf][3]);
            }
        __syncthreads();

        // reduce 8 partials + epilogue (first 256 threads)
        if (tid < 256) {
            float s[8] = {0.f, 0.f, 0.f, 0.f, 0.f, 0.f, 0.f, 0.f};
            #pragma unroll
            for (int ww = 0; ww < 8; ww++) {
                float4 r0 = *(const float4*)&Red[(ww * 128 + em) * RS + ecol];
                float4 r1 = *(const float4*)&Red[(ww * 128 + em) * RS + ecol + 4];
                s[0] += r0.x; s[1] += r0.y; s[2] += r0.z; s[3] += r0.w;
                s[4] += r1.x; s[5] += r1.y; s[6] += r1.z; s[7] += r1.w;
            }
            float v[8];
            v[0] = tanhf(s[0] + xpA.x + bhA.x);
            v[1] = tanhf(s[1] + xpA.y + bhA.y);
            v[2] = tanhf(s[2] + xpA.z + bhA.z);
            v[3] = tanhf(s[3] + xpA.w + bhA.w);
            v[4] = tanhf(s[4] + xpB.x + bhB.x);
            v[5] = tanhf(s[5] + xpB.y + bhB.y);
            v[6] = tanhf(s[6] + xpB.z + bhB.z);
            v[7] = tanhf(s[7] + xpB.w + bhB.w);

            // exact h_e output (natural order)
            size_t orow = ((size_t)em * Tt + t) * 1024 + gc;
            *(float4*)&h_e[orow]     = make_float4(v[0], v[1], v[2], v[3]);
            *(float4*)&h_e[orow + 4] = make_float4(v[4], v[5], v[6], v[7]);

            // rounded + k-pair-permuted copies: recurrence state + phase-3 input
            float r[8];
            #pragma unroll
            for (int j = 0; j < 8; j++) r[j] = rndt(v[j]);
            float4 pA = make_float4(r[0], r[4], r[1], r[5]);
            float4 pB = make_float4(r[2], r[6], r[3], r[7]);
            *(float4*)&g_hr[orow]     = pA;
            *(float4*)&g_hr[orow + 4] = pB;
            *(float4*)&hd[em * 1024 + gc]     = pA;
            *(float4*)&hd[em * 1024 + gc + 4] = pB;
        }

        // grid barrier (monotonic counter; reset each launch by init_k)
        __threadfence();
        __syncthreads();
        if (tid == 0) {
            atomicAdd(&g_bar, 1u);
            unsigned tgt = (unsigned)(RCg * (t + 1)), vv;
            do {
                asm volatile("ld.acquire.gpu.u32 %0, [%1];" : "=r"(vv) : "l"(&g_bar));
            } while (vv < tgt);
        }
        __syncthreads();
    }
}

// -------- launch ---------------------------------------------------------
extern "C" void kernel_launch(void* const* d_in, const int* in_sizes, int n_in,
                              void* d_out, int out_size) {
    (void)in_sizes; (void)n_in; (void)out_size;
    const int*   x      = (const int*)d_in[0];
    const float* h_init = (const float*)d_in[1];
    const float* embed  = (const float*)d_in[2];
    const float* Wx     = (const float*)d_in[3];
    const float* bx     = (const float*)d_in[4];
    const float* Wh     = (const float*)d_in[5];
    const float* bh     = (const float*)d_in[6];
    const float* Wo     = (const float*)d_in[7];
    const float* bo     = (const float*)d_in[8];

    float* out = (float*)d_out;
    float* h_e = out;                       // [B][T][H]
    float* y_e = out + (size_t)BT * Hh;     // [B][T][V]

    const int SMEM_P = (3 * ASZ + 3 * BSZ) * 4 + 128 * 8;   // 101376 + 1024 = 102400
    const int SMEM_R = (16576 + 20480) * 4;                 // 148224

    cudaFuncSetAttribute(gemm_k<true>,  cudaFuncAttributeMaxDynamicSharedMemorySize, SMEM_P);
    cudaFuncSetAttribute(gemm_k<false>, cudaFuncAttributeMaxDynamicSharedMemorySize, SMEM_P);
    cudaFuncSetAttribute(rnn_k,         cudaFuncAttributeMaxDynamicSharedMemorySize, SMEM_R);

    void* xp_ptr = nullptr;   cudaGetSymbolAddress(&xp_ptr, g_xp);
    void* hr_ptr = nullptr;   cudaGetSymbolAddress(&hr_ptr, g_hr);
    void* emb_ptr = nullptr;  cudaGetSymbolAddress(&emb_ptr, g_embr);
    void* wx_ptr = nullptr;   cudaGetSymbolAddress(&wx_ptr, g_Wxr);
    void* wo_ptr = nullptr;   cudaGetSymbolAddress(&wo_ptr, g_Wor);

    // 1. round+permute embed/Wx/Wo; reset barrier; h_init -> g_h[0]
    prep_k<<<512, 256>>>(embed, Wx, Wo);
    init_k<<<128, 256>>>(h_init);
    // 2. xp[t][b][:] = embed_r[x[b][t]] @ Wx_r^T + bx
    gemm_k<true><<<dim3(16, 512), 256, SMEM_P>>>((const float*)emb_ptr, x,
                                                 (const float*)wx_ptr, bx, (float*)xp_ptr);
    // 3. serial recurrence -> h_e (+ rounded copies)
    rnn_k<<<RCg, 512, SMEM_R>>>(Wh, bh, h_e);
    // 4. y = h_r @ Wo_r^T + bo
    gemm_k<false><<<dim3(16, 512), 256, SMEM_P>>>((const float*)hr_ptr, nullptr,
                                                  (const float*)wo_ptr, bo, y_e);
}

// round 5
// speedup vs baseline: 1.5291x; 1.5291x over previous
#include <cuda_runtime.h>
#include <cstdint>
#include <math.h>

// Problem dims (fixed)
#define Bb 128
#define Tt 512
#define Hh 1024
#define BT (Bb*Tt)

// -------- device-global scratch ------------------------------------------
__device__ float g_xp[(size_t)BT * Hh];    // 256 MB input projections [T][B][H]
__device__ float g_hr[(size_t)BT * Hh];    // 256 MB rounded+permuted h [B][T][H]
__device__ float g_h[2][Bb * Hh];          // h double buffer (rounded+permuted)
__device__ float g_embr[1024 * 1024];      // rounded+permuted embed table
__device__ float g_Wxr[1024 * 1024];       // rounded+permuted Wx
__device__ float g_Wor[1024 * 1024];       // rounded+permuted Wo
__device__ unsigned int g_barA[4 * 32];    // 4 barrier counters, 128B apart

// -------- helpers --------------------------------------------------------
__device__ __forceinline__ uint32_t f2t(float x) {
    uint32_t u; asm("cvt.rna.tf32.f32 %0, %1;" : "=r"(u) : "f"(x));
    return u;
}
__device__ __forceinline__ float rndt(float x) { return __uint_as_float(f2t(x)); }
// k-pair interleave within 8-blocks: (j, j+4) -> positions (2j, 2j+1)
__device__ __forceinline__ int pig(int k) {
    int j = k & 7;
    return (k & ~7) | ((j < 4) ? (2 * j) : (2 * (j - 4) + 1));
}
__device__ __forceinline__ void cp16(float* s, const float* g) {
    uint32_t sa = (uint32_t)__cvta_generic_to_shared(s);
    asm volatile("cp.async.cg.shared.global [%0], [%1], 16;\n" :: "r"(sa), "l"(g));
}
__device__ __forceinline__ void cp_commit() { asm volatile("cp.async.commit_group;\n"); }
template<int N> __device__ __forceinline__ void cp_wait() {
    asm volatile("cp.async.wait_group %0;\n" :: "n"(N));
}
__device__ __forceinline__ void mma8(float* c, const uint32_t* a, const uint32_t* b) {
    asm volatile(
        "mma.sync.aligned.m16n8k8.row.col.f32.tf32.tf32.f32 "
        "{%0,%1,%2,%3},{%4,%5,%6,%7},{%8,%9},{%0,%1,%2,%3};"
        : "+f"(c[0]), "+f"(c[1]), "+f"(c[2]), "+f"(c[3])
        : "r"(a[0]), "r"(a[1]), "r"(a[2]), "r"(a[3]), "r"(b[0]), "r"(b[1]));
}

// -------- prologue: round+permute embed, Wx, Wo --------------------------
__global__ void prep_k(const float* __restrict__ e, const float* __restrict__ wx,
                       const float* __restrict__ wo) {
    int st = gridDim.x * blockDim.x;
    for (int i = blockIdx.x * blockDim.x + threadIdx.x; i < 1024 * 1024; i += st) {
        int r = i >> 10, k = i & 1023;
        int d = (r << 10) | pig(k);
        g_embr[d] = rndt(e[i]);
        g_Wxr[d]  = rndt(wx[i]);
        g_Wor[d]  = rndt(wo[i]);
    }
}

__global__ void init_k(const float* __restrict__ h0) {
    int i = blockIdx.x * blockDim.x + threadIdx.x;
    if (i < 128) g_barA[i] = 0u;
    for (int j = i; j < Bb * Hh; j += gridDim.x * blockDim.x) {
        int r = j >> 10, k = j & 1023;
        g_h[0][(r << 10) | pig(k)] = rndt(h0[j]);
    }
}

// -------- phase GEMM: C[m][n] = sum_k A[m][k]*W[n][k] + bias[n] ----------
// Tile 128x64xK32, 256 threads = 8 warps (4M x 2N) of 32x32.
// 3-stage cp.async ring, prefetch depth 2.
#define PS 44
#define ASZ 5632
#define BSZ 2816

__device__ __forceinline__ void stage_p(const float* const* rp, const float* __restrict__ W,
                                        int n0, int k0, float* As, float* Bs, int tid) {
    #pragma unroll
    for (int j = 0; j < 4; j++) {
        int c = j * 256 + tid; int r = c >> 3, o = c & 7;
        cp16(As + r * PS + o * 4, rp[r] + k0 + o * 4);
    }
    #pragma unroll
    for (int j = 0; j < 2; j++) {
        int c = j * 256 + tid; int r = c >> 3, o = c & 7;
        cp16(Bs + r * PS + o * 4, W + (size_t)(n0 + r) * 1024 + k0 + o * 4);
    }
}

template<bool GATHER>
__global__ __launch_bounds__(256, 2) void gemm_k(const float* __restrict__ Ab,
                                                 const int* __restrict__ tok,
                                                 const float* __restrict__ W,
                                                 const float* __restrict__ bias,
                                                 float* __restrict__ C) {
    extern __shared__ float sm[];
    float* As = sm;
    float* Bs = sm + 3 * ASZ;
    const float** rp = (const float**)(sm + 3 * ASZ + 3 * BSZ);

    const int tid = threadIdx.x;
    if (tid < 128) {
        if (GATHER) rp[tid] = Ab + (size_t)tok[tid * Tt + blockIdx.y] * 1024;
        else        rp[tid] = Ab + ((size_t)blockIdx.y * 128 + tid) * 1024;
    }
    __syncthreads();

    const int n0 = blockIdx.x * 64;
    const int lane = tid & 31, w = tid >> 5;
    const int g = lane >> 2, t4 = lane & 3;
    const int wm = (w >> 1) * 32, wn = (w & 1) * 32;

    float acc[2][4][4];
    #pragma unroll
    for (int a = 0; a < 2; a++)
        #pragma unroll
        for (int b = 0; b < 4; b++)
            #pragma unroll
            for (int c = 0; c < 4; c++) acc[a][b][c] = 0.f;

    stage_p(rp, W, n0, 0, As, Bs, tid);              cp_commit();
    stage_p(rp, W, n0, 32, As + ASZ, Bs + BSZ, tid); cp_commit();

    int buf = 0;
    for (int ks = 0; ks < 32; ks++) {
        if (ks < 30) cp_wait<1>(); else cp_wait<0>();
        __syncthreads();
        if (ks < 30) {
            int nb = buf + 2; if (nb >= 3) nb -= 3;
            stage_p(rp, W, n0, (ks + 2) * 32, As + nb * ASZ, Bs + nb * BSZ, tid);
            cp_commit();
        }
        const float* A_ = As + buf * ASZ;
        const float* B_ = Bs + buf * BSZ;
        #pragma unroll
        for (int kk = 0; kk < 32; kk += 8) {
            uint32_t a[2][4];
            #pragma unroll
            for (int mi = 0; mi < 2; mi++) {
                float2 p0 = *(const float2*)&A_[(wm + mi * 16 + g) * PS + kk + 2 * t4];
                float2 p1 = *(const float2*)&A_[(wm + mi * 16 + 8 + g) * PS + kk + 2 * t4];
                a[mi][0] = __float_as_uint(p0.x); a[mi][1] = __float_as_uint(p1.x);
                a[mi][2] = __float_as_uint(p0.y); a[mi][3] = __float_as_uint(p1.y);
            }
            #pragma unroll
            for (int ni = 0; ni < 4; ni++) {
                float2 q = *(const float2*)&B_[(wn + ni * 8 + g) * PS + kk + 2 * t4];
                uint32_t b[2] = { __float_as_uint(q.x), __float_as_uint(q.y) };
                mma8(acc[0][ni], a[0], b);
                mma8(acc[1][ni], a[1], b);
            }
        }
        buf++; if (buf >= 3) buf -= 3;
    }

    const int m0 = blockIdx.y * 128;
    #pragma unroll
    for (int ni = 0; ni < 4; ni++) {
        int nc = n0 + wn + ni * 8 + 2 * t4;
        float b0 = bias[nc], b1 = bias[nc + 1];
        #pragma unroll
        for (int mi = 0; mi < 2; mi++) {
            int r0 = m0 + wm + mi * 16 + g;
            *(float2*)&C[(size_t)r0 * 1024 + nc] =
                make_float2(acc[mi][ni][0] + b0, acc[mi][ni][1] + b1);
            *(float2*)&C[(size_t)(r0 + 8) * 1024 + nc] =
                make_float2(acc[mi][ni][2] + b0, acc[mi][ni][3] + b1);
        }
    }
}

// -------- persistent recurrence kernel (v2) ------------------------------
// 128 CTAs = 4(M-quarters of 32 rows) x 32(N-groups of 32 cols), 256 thr.
// Wh slice 32x1024 resident in smem; warp w owns K-eighth [128w,+128).
// h staged via cp.async in 32-float chunks (full-line coalesced), per-warp
// commit groups (no cross-warp sync in mainloop). 8 K-partials reduced in
// smem (Red aliases stage area). 4-counter grid barrier per step.
#define WS2 1036            // Whs row stride (floats)
#define STG 36              // stage/Red row stride (floats)
#define WHS_F (32 * WS2)    // 33152 floats
#define STGW (2 * 32 * STG) // 2304 floats per warp (2 buffers x 32x36)
#define SMEM_RF (WHS_F + 8 * STGW)  // 51584 floats = 206336 B

__global__ __launch_bounds__(256, 1) void rnn_k(const float* __restrict__ Wh,
                                                const float* __restrict__ bh,
                                                float* __restrict__ h_e) {
    extern __shared__ float sm[];
    float* Whs = sm;                       // 32 x 1036
    float* Stg = sm + WHS_F;               // 8 warps x 2 x (32x36); Red aliases

    const int tid = threadIdx.x;
    const int nq = blockIdx.x & 31, mq = blockIdx.x >> 5;
    const int nb = nq * 32, mb = mq * 32;

    // build rounded+permuted Wh slice (32 output cols) in smem, once
    for (int i = tid; i < 32 * 1024; i += 256) {
        int n = i >> 10, k = i & 1023;
        Whs[n * WS2 + pig(k)] = rndt(Wh[(size_t)(nb + n) * 1024 + k]);
    }
    __syncthreads();

    const int lane = tid & 31, w = tid >> 5;
    const int g = lane >> 2, t4 = lane & 3;
    const int kb = w * 128;
    float* SB = Stg + w * STGW;            // this warp's 2 stage buffers
    const int srow = lane >> 3, su = lane & 7;   // stage mapping

    // epilogue mapping (tid<128): row er, cols [gcb, gcb+8)
    const int er = tid & 31, eblk = tid >> 5;    // eblk 0..3 for tid<128
    const int gr = mb + er, gcb = nb + eblk * 8;
    float bhv[8];
    if (tid < 128) {
        float4 q0 = *(const float4*)&bh[gcb];
        float4 q1 = *(const float4*)&bh[gcb + 4];
        bhv[0]=q0.x; bhv[1]=q0.y; bhv[2]=q0.z; bhv[3]=q0.w;
        bhv[4]=q1.x; bhv[5]=q1.y; bhv[6]=q1.z; bhv[7]=q1.w;
    }

    for (int t = 0; t < Tt; t++) {
        const float* hs = g_h[t & 1];
        float* hd = g_h[(t + 1) & 1];
        const float* gsrc = hs + (size_t)mb * 1024 + kb;

        // xp prefetch (DRAM latency hidden under GEMM)
        float4 xq0, xq1;
        if (tid < 128) {
            xq0 = *(const float4*)&g_xp[(size_t)(t * 128 + gr) * 1024 + gcb];
            xq1 = *(const float4*)&g_xp[(size_t)(t * 128 + gr) * 1024 + gcb + 4];
        }

        float acc[2][4][4];
        #pragma unroll
        for (int a = 0; a < 2; a++)
            #pragma unroll
            for (int b = 0; b < 4; b++)
                #pragma unroll
                for (int c = 0; c < 4; c++) acc[a][b][c] = 0.f;

        // prologue: stage chunks 0,1 (each 32 k-floats, full-line coalesced)
        #pragma unroll
        for (int cc = 0; cc < 2; cc++) {
            #pragma unroll
            for (int j = 0; j < 8; j++) {
                int r = srow + 4 * j;
                cp16(SB + cc * (32 * STG) + r * STG + su * 4,
                     gsrc + (size_t)r * 1024 + cc * 32 + su * 4);
            }
            cp_commit();
        }

        #pragma unroll
        for (int c = 0; c < 4; c++) {
            if (c < 3) cp_wait<1>(); else cp_wait<0>();
            __syncwarp();
            const float* B_ = SB + (c & 1) * (32 * STG);
            const float* Wrow = Whs + kb + c * 32 + 2 * t4;
            #pragma unroll
            for (int kf = 0; kf < 4; kf++) {
                uint32_t a[2][4];
                #pragma unroll
                for (int mi = 0; mi < 2; mi++) {
                    float2 p0 = *(const float2*)&B_[(mi * 16 + g) * STG + kf * 8 + 2 * t4];
                    float2 p1 = *(const float2*)&B_[(mi * 16 + 8 + g) * STG + kf * 8 + 2 * t4];
                    a[mi][0] = __float_as_uint(p0.x); a[mi][1] = __float_as_uint(p1.x);
                    a[mi][2] = __float_as_uint(p0.y); a[mi][3] = __float_as_uint(p1.y);
                }
                #pragma unroll
                for (int ni = 0; ni < 4; ni++) {
                    float2 q = *(const float2*)&Wrow[(ni * 8 + g) * WS2 + kf * 8];
                    uint32_t b[2] = { __float_as_uint(q.x), __float_as_uint(q.y) };
                    mma8(acc[0][ni], a[0], b);
                    mma8(acc[1][ni], a[1], b);
                }
            }
            if (c < 2) {   // stage chunk c+2 into the buffer just consumed
                __syncwarp();
                #pragma unroll
                for (int j = 0; j < 8; j++) {
                    int r = srow + 4 * j;
                    cp16(SB + (c & 1) * (32 * STG) + r * STG + su * 4,
                         gsrc + (size_t)r * 1024 + (c + 2) * 32 + su * 4);
                }
                cp_commit();
            }
        }

        // all warps done with their stage buffers -> write K-partials (alias)
        __syncthreads();
        float* Redw = Stg + w * (32 * STG);
        #pragma unroll
        for (int mi = 0; mi < 2; mi++)
            #pragma unroll
            for (int ni = 0; ni < 4; ni++) {
                int nc = ni * 8 + 2 * t4;
                *(float2*)&Redw[(mi * 16 + g) * STG + nc] =
                    make_float2(acc[mi][ni][0], acc[mi][ni][1]);
                *(float2*)&Redw[(mi * 16 + 8 + g) * STG + nc] =
                    make_float2(acc[mi][ni][2], acc[mi][ni][3]);
            }
        __syncthreads();

        // reduce 8 partials + epilogue (tid < 128)
        if (tid < 128) {
            float s[8] = {0.f,0.f,0.f,0.f,0.f,0.f,0.f,0.f};
            #pragma unroll
            for (int ww = 0; ww < 8; ww++) {
                const float* Rr = Stg + ww * (32 * STG) + er * STG + eblk * 8;
                float4 r0 = *(const float4*)&Rr[0];
                float4 r1 = *(const float4*)&Rr[4];
                s[0] += r0.x; s[1] += r0.y; s[2] += r0.z; s[3] += r0.w;
                s[4] += r1.x; s[5] += r1.y; s[6] += r1.z; s[7] += r1.w;
            }
            float v[8];
            v[0] = tanhf(s[0] + xq0.x + bhv[0]);
            v[1] = tanhf(s[1] + xq0.y + bhv[1]);
            v[2] = tanhf(s[2] + xq0.z + bhv[2]);
            v[3] = tanhf(s[3] + xq0.w + bhv[3]);
            v[4] = tanhf(s[4] + xq1.x + bhv[4]);
            v[5] = tanhf(s[5] + xq1.y + bhv[5]);
            v[6] = tanhf(s[6] + xq1.z + bhv[6]);
            v[7] = tanhf(s[7] + xq1.w + bhv[7]);

            // exact h_e output (natural order, [b][t][h])
            size_t orow = ((size_t)gr * Tt + t) * 1024 + gcb;
            *(float4*)&h_e[orow]     = make_float4(v[0], v[1], v[2], v[3]);
            *(float4*)&h_e[orow + 4] = make_float4(v[4], v[5], v[6], v[7]);

            // rounded + k-pair-permuted copies: state + phase-3 input
            float r[8];
            #pragma unroll
            for (int j = 0; j < 8; j++) r[j] = rndt(v[j]);
            float4 pA = make_float4(r[0], r[4], r[1], r[5]);
            float4 pB = make_float4(r[2], r[6], r[3], r[7]);
            *(float4*)&g_hr[orow]     = pA;
            *(float4*)&g_hr[orow + 4] = pB;
            *(float4*)&hd[(size_t)gr * 1024 + gcb]     = pA;
            *(float4*)&hd[(size_t)gr * 1024 + gcb + 4] = pB;
        }

        // grid barrier: 4 padded counters (by mq), poll all
        __threadfence();
        __syncthreads();
        if (tid == 0) {
            atomicAdd(&g_barA[mq * 32], 1u);
            unsigned tgt = (unsigned)(32 * (t + 1));
            for (;;) {
                unsigned v0, v1, v2, v3;
                asm volatile("ld.acquire.gpu.u32 %0, [%1];" : "=r"(v0) : "l"(&g_barA[0]));
                asm volatile("ld.acquire.gpu.u32 %0, [%1];" : "=r"(v1) : "l"(&g_barA[32]));
                asm volatile("ld.acquire.gpu.u32 %0, [%1];" : "=r"(v2) : "l"(&g_barA[64]));
                asm volatile("ld.acquire.gpu.u32 %0, [%1];" : "=r"(v3) : "l"(&g_barA[96]));
                if (v0 >= tgt && v1 >= tgt && v2 >= tgt && v3 >= tgt) break;
            }
        }
        __syncthreads();
    }
}

// -------- launch ---------------------------------------------------------
extern "C" void kernel_launch(void* const* d_in, const int* in_sizes, int n_in,
                              void* d_out, int out_size) {
    (void)in_sizes; (void)n_in; (void)out_size;
    const int*   x      = (const int*)d_in[0];
    const float* h_init = (const float*)d_in[1];
    const float* embed  = (const float*)d_in[2];
    const float* Wx     = (const float*)d_in[3];
    const float* bx     = (const float*)d_in[4];
    const float* Wh     = (const float*)d_in[5];
    const float* bh     = (const float*)d_in[6];
    const float* Wo     = (const float*)d_in[7];
    const float* bo     = (const float*)d_in[8];

    float* out = (float*)d_out;
    float* h_e = out;                       // [B][T][H]
    float* y_e = out + (size_t)BT * Hh;     // [B][T][V]

    const int SMEM_P = (3 * ASZ + 3 * BSZ) * 4 + 128 * 8;   // 102400
    const int SMEM_R = SMEM_RF * 4;                         // 206336

    cudaFuncSetAttribute(gemm_k<true>,  cudaFuncAttributeMaxDynamicSharedMemorySize, SMEM_P);
    cudaFuncSetAttribute(gemm_k<false>, cudaFuncAttributeMaxDynamicSharedMemorySize, SMEM_P);
    cudaFuncSetAttribute(rnn_k,         cudaFuncAttributeMaxDynamicSharedMemorySize, SMEM_R);

    void* xp_ptr = nullptr;   cudaGetSymbolAddress(&xp_ptr, g_xp);
    void* hr_ptr = nullptr;   cudaGetSymbolAddress(&hr_ptr, g_hr);
    void* emb_ptr = nullptr;  cudaGetSymbolAddress(&emb_ptr, g_embr);
    void* wx_ptr = nullptr;   cudaGetSymbolAddress(&wx_ptr, g_Wxr);
    void* wo_ptr = nullptr;   cudaGetSymbolAddress(&wo_ptr, g_Wor);

    // 1. round+permute embed/Wx/Wo; reset barriers; h_init -> g_h[0]
    prep_k<<<512, 256>>>(embed, Wx, Wo);
    init_k<<<128, 256>>>(h_init);
    // 2. xp[t][b][:] = embed_r[x[b][t]] @ Wx_r^T + bx
    gemm_k<true><<<dim3(16, 512), 256, SMEM_P>>>((const float*)emb_ptr, x,
                                                 (const float*)wx_ptr, bx, (float*)xp_ptr);
    // 3. serial recurrence -> h_e (+ rounded copies)
    rnn_k<<<128, 256, SMEM_R>>>(Wh, bh, h_e);
    // 4. y = h_r @ Wo_r^T + bo
    gemm_k<false><<<dim3(16, 512), 256, SMEM_P>>>((const float*)hr_ptr, nullptr,
                                                  (const float*)wo_ptr, bo, y_e);
}

// round 7
// speedup vs baseline: 1.7259x; 1.1287x over previous
#include <cuda_runtime.h>
#include <cstdint>
#include <math.h>

// Problem dims (fixed)
#define Bb 128
#define Tt 512
#define Hh 1024
#define BT (Bb*Tt)

// -------- device-global scratch ------------------------------------------
__device__ float g_xp[(size_t)BT * Hh];    // 256 MB input projections [T][B][H]
__device__ float g_hr[(size_t)BT * Hh];    // 256 MB rounded+permuted h [B][T][H]
__device__ float g_h[2][Bb * Hh];          // h double buffer (rounded+permuted)
__device__ float g_embr[1024 * 1024];      // rounded+permuted embed table
__device__ float g_Wxr[1024 * 1024];       // rounded+permuted Wx
__device__ float g_Wor[1024 * 1024];       // rounded+permuted Wo
__device__ unsigned int g_barA[4 * 32];    // 4 per-group counters, 128B apart

// -------- helpers --------------------------------------------------------
__device__ __forceinline__ uint32_t f2t(float x) {
    uint32_t u; asm("cvt.rna.tf32.f32 %0, %1;" : "=r"(u) : "f"(x));
    return u;
}
__device__ __forceinline__ float rndt(float x) { return __uint_as_float(f2t(x)); }
// k-pair interleave within 8-blocks: (j, j+4) -> positions (2j, 2j+1)
__device__ __forceinline__ int pig(int k) {
    int j = k & 7;
    return (k & ~7) | ((j < 4) ? (2 * j) : (2 * (j - 4) + 1));
}
__device__ __forceinline__ void cp16(float* s, const float* g) {
    uint32_t sa = (uint32_t)__cvta_generic_to_shared(s);
    asm volatile("cp.async.cg.shared.global [%0], [%1], 16;\n" :: "r"(sa), "l"(g));
}
__device__ __forceinline__ void cp_commit() { asm volatile("cp.async.commit_group;\n"); }
template<int N> __device__ __forceinline__ void cp_wait() {
    asm volatile("cp.async.wait_group %0;\n" :: "n"(N));
}
__device__ __forceinline__ void mma8(float* c, const uint32_t* a, const uint32_t* b) {
    asm volatile(
        "mma.sync.aligned.m16n8k8.row.col.f32.tf32.tf32.f32 "
        "{%0,%1,%2,%3},{%4,%5,%6,%7},{%8,%9},{%0,%1,%2,%3};"
        : "+f"(c[0]), "+f"(c[1]), "+f"(c[2]), "+f"(c[3])
        : "r"(a[0]), "r"(a[1]), "r"(a[2]), "r"(a[3]), "r"(b[0]), "r"(b[1]));
}

// -------- prologue: round+permute embed, Wx, Wo --------------------------
__global__ void prep_k(const float* __restrict__ e, const float* __restrict__ wx,
                       const float* __restrict__ wo) {
    int st = gridDim.x * blockDim.x;
    for (int i = blockIdx.x * blockDim.x + threadIdx.x; i < 1024 * 1024; i += st) {
        int r = i >> 10, k = i & 1023;
        int d = (r << 10) | pig(k);
        g_embr[d] = rndt(e[i]);
        g_Wxr[d]  = rndt(wx[i]);
        g_Wor[d]  = rndt(wo[i]);
    }
}

__global__ void init_k(const float* __restrict__ h0) {
    int i = blockIdx.x * blockDim.x + threadIdx.x;
    if (i < 128) g_barA[i] = 0u;
    for (int j = i; j < Bb * Hh; j += gridDim.x * blockDim.x) {
        int r = j >> 10, k = j & 1023;
        g_h[0][(r << 10) | pig(k)] = rndt(h0[j]);
    }
}

// -------- phase GEMM: C[m][n] = sum_k A[m][k]*W[n][k] + bias[n] ----------
// Tile 128x64xK32, 256 threads = 8 warps (4M x 2N) of 32x32.
// 3-stage cp.async ring, prefetch depth 2.
#define PS 44
#define ASZ 5632
#define BSZ 2816

__device__ __forceinline__ void stage_p(const float* const* rp, const float* __restrict__ W,
                                        int n0, int k0, float* As, float* Bs, int tid) {
    #pragma unroll
    for (int j = 0; j < 4; j++) {
        int c = j * 256 + tid; int r = c >> 3, o = c & 7;
        cp16(As + r * PS + o * 4, rp[r] + k0 + o * 4);
    }
    #pragma unroll
    for (int j = 0; j < 2; j++) {
        int c = j * 256 + tid; int r = c >> 3, o = c & 7;
        cp16(Bs + r * PS + o * 4, W + (size_t)(n0 + r) * 1024 + k0 + o * 4);
    }
}

template<bool GATHER>
__global__ __launch_bounds__(256, 2) void gemm_k(const float* __restrict__ Ab,
                                                 const int* __restrict__ tok,
                                                 const float* __restrict__ W,
                                                 const float* __restrict__ bias,
                                                 float* __restrict__ C) {
    extern __shared__ float sm[];
    float* As = sm;
    float* Bs = sm + 3 * ASZ;
    const float** rp = (const float**)(sm + 3 * ASZ + 3 * BSZ);

    const int tid = threadIdx.x;
    if (tid < 128) {
        if (GATHER) rp[tid] = Ab + (size_t)tok[tid * Tt + blockIdx.y] * 1024;
        else        rp[tid] = Ab + ((size_t)blockIdx.y * 128 + tid) * 1024;
    }
    __syncthreads();

    const int n0 = blockIdx.x * 64;
    const int lane = tid & 31, w = tid >> 5;
    const int g = lane >> 2, t4 = lane & 3;
    const int wm = (w >> 1) * 32, wn = (w & 1) * 32;

    float acc[2][4][4];
    #pragma unroll
    for (int a = 0; a < 2; a++)
        #pragma unroll
        for (int b = 0; b < 4; b++)
            #pragma unroll
            for (int c = 0; c < 4; c++) acc[a][b][c] = 0.f;

    stage_p(rp, W, n0, 0, As, Bs, tid);              cp_commit();
    stage_p(rp, W, n0, 32, As + ASZ, Bs + BSZ, tid); cp_commit();

    int buf = 0;
    for (int ks = 0; ks < 32; ks++) {
        if (ks < 30) cp_wait<1>(); else cp_wait<0>();
        __syncthreads();
        if (ks < 30) {
            int nb = buf + 2; if (nb >= 3) nb -= 3;
            stage_p(rp, W, n0, (ks + 2) * 32, As + nb * ASZ, Bs + nb * BSZ, tid);
            cp_commit();
        }
        const float* A_ = As + buf * ASZ;
        const float* B_ = Bs + buf * BSZ;
        #pragma unroll
        for (int kk = 0; kk < 32; kk += 8) {
            uint32_t a[2][4];
            #pragma unroll
            for (int mi = 0; mi < 2; mi++) {
                float2 p0 = *(const float2*)&A_[(wm + mi * 16 + g) * PS + kk + 2 * t4];
                float2 p1 = *(const float2*)&A_[(wm + mi * 16 + 8 + g) * PS + kk + 2 * t4];
                a[mi][0] = __float_as_uint(p0.x); a[mi][1] = __float_as_uint(p1.x);
                a[mi][2] = __float_as_uint(p0.y); a[mi][3] = __float_as_uint(p1.y);
            }
            #pragma unroll
            for (int ni = 0; ni < 4; ni++) {
                float2 q = *(const float2*)&B_[(wn + ni * 8 + g) * PS + kk + 2 * t4];
                uint32_t b[2] = { __float_as_uint(q.x), __float_as_uint(q.y) };
                mma8(acc[0][ni], a[0], b);
                mma8(acc[1][ni], a[1], b);
            }
        }
        buf++; if (buf >= 3) buf -= 3;
    }

    const int m0 = blockIdx.y * 128;
    #pragma unroll
    for (int ni = 0; ni < 4; ni++) {
        int nc = n0 + wn + ni * 8 + 2 * t4;
        float b0 = bias[nc], b1 = bias[nc + 1];
        #pragma unroll
        for (int mi = 0; mi < 2; mi++) {
            int r0 = m0 + wm + mi * 16 + g;
            *(float2*)&C[(size_t)r0 * 1024 + nc] =
                make_float2(acc[mi][ni][0] + b0, acc[mi][ni][1] + b1);
            *(float2*)&C[(size_t)(r0 + 8) * 1024 + nc] =
                make_float2(acc[mi][ni][2] + b0, acc[mi][ni][3] + b1);
        }
    }
}

// -------- persistent recurrence kernel (v4) ------------------------------
// 128 CTAs = 4 independent M-groups (32 batch rows each) x 32 N-CTAs.
// Per-group barrier (32 arrivals). K-partials go into buffer 0 of each
// warp's OWN stage pair (warp-private; buffer 0's last read is chunk c=2).
// Visibility: storing threads __threadfence() after hd stores (cheap, L2),
// then bar.sync, then tid0 relaxed atomicAdd; h_e/g_hr DRAM stores and
// xp(t+1) prefetch overlap the acquire-poll.
#define WS2 1036            // Whs row stride (floats)
#define STG 36              // stage/Red row stride (floats)
#define WHS_F (32 * WS2)    // 33152 floats
#define STGW (2 * 32 * STG) // 2304 floats per warp (2 buffers x 32x36)
#define SMEM_RF (WHS_F + 8 * STGW)  // 51584 floats = 206336 B

__global__ __launch_bounds__(256, 1) void rnn_k(const float* __restrict__ Wh,
                                                const float* __restrict__ bh,
                                                float* __restrict__ h_e) {
    extern __shared__ float sm[];
    float* Whs = sm;                       // 32 x 1036
    float* Stg = sm + WHS_F;               // 8 warps x 2 x (32x36)

    const int tid = threadIdx.x;
    const int nq = blockIdx.x & 31, mq = blockIdx.x >> 5;
    const int nb = nq * 32, mb = mq * 32;
    unsigned int* mybar = &g_barA[mq * 32];

    // build rounded+permuted Wh slice (32 output cols) in smem, once
    for (int i = tid; i < 32 * 1024; i += 256) {
        int n = i >> 10, k = i & 1023;
        Whs[n * WS2 + pig(k)] = rndt(Wh[(size_t)(nb + n) * 1024 + k]);
    }
    __syncthreads();

    const int lane = tid & 31, w = tid >> 5;
    const int g = lane >> 2, t4 = lane & 3;
    const int kb = w * 128;
    float* SB = Stg + w * STGW;            // this warp's 2 stage buffers
    const int srow = lane >> 3, su = lane & 7;   // stage mapping

    // epilogue mapping (tid<128): row er, cols [gcb, gcb+8)
    const int er = tid & 31, eblk = tid >> 5;    // eblk 0..3 for tid<128
    const int gr = mb + er, gcb = nb + eblk * 8;
    float bhv[8];
    float4 xq0, xq1;
    if (tid < 128) {
        float4 q0 = *(const float4*)&bh[gcb];
        float4 q1 = *(const float4*)&bh[gcb + 4];
        bhv[0]=q0.x; bhv[1]=q0.y; bhv[2]=q0.z; bhv[3]=q0.w;
        bhv[4]=q1.x; bhv[5]=q1.y; bhv[6]=q1.z; bhv[7]=q1.w;
        // prefetch xp for t=0
        xq0 = *(const float4*)&g_xp[(size_t)gr * 1024 + gcb];
        xq1 = *(const float4*)&g_xp[(size_t)gr * 1024 + gcb + 4];
    }

    for (int t = 0; t < Tt; t++) {
        const float* hs = g_h[t & 1];
        float* hd = g_h[(t + 1) & 1];
        const float* gsrc = hs + (size_t)mb * 1024 + kb;

        float acc[2][4][4];
        #pragma unroll
        for (int a = 0; a < 2; a++)
            #pragma unroll
            for (int b = 0; b < 4; b++)
                #pragma unroll
                for (int c = 0; c < 4; c++) acc[a][b][c] = 0.f;

        // prologue: stage chunks 0,1 (each 32 k-floats, full-line coalesced)
        #pragma unroll
        for (int cc = 0; cc < 2; cc++) {
            #pragma unroll
            for (int j = 0; j < 8; j++) {
                int r = srow + 4 * j;
                cp16(SB + cc * (32 * STG) + r * STG + su * 4,
                     gsrc + (size_t)r * 1024 + cc * 32 + su * 4);
            }
            cp_commit();
        }

        #pragma unroll
        for (int c = 0; c < 4; c++) {
            if (c < 3) cp_wait<1>(); else cp_wait<0>();
            __syncwarp();
            const float* B_ = SB + (c & 1) * (32 * STG);
            const float* Wrow = Whs + kb + c * 32 + 2 * t4;
            #pragma unroll
            for (int kf = 0; kf < 4; kf++) {
                uint32_t a[2][4];
                #pragma unroll
                for (int mi = 0; mi < 2; mi++) {
                    float2 p0 = *(const float2*)&B_[(mi * 16 + g) * STG + kf * 8 + 2 * t4];
                    float2 p1 = *(const float2*)&B_[(mi * 16 + 8 + g) * STG + kf * 8 + 2 * t4];
                    a[mi][0] = __float_as_uint(p0.x); a[mi][1] = __float_as_uint(p1.x);
                    a[mi][2] = __float_as_uint(p0.y); a[mi][3] = __float_as_uint(p1.y);
                }
                #pragma unroll
                for (int ni = 0; ni < 4; ni++) {
                    float2 q = *(const float2*)&Wrow[(ni * 8 + g) * WS2 + kf * 8];
                    uint32_t b[2] = { __float_as_uint(q.x), __float_as_uint(q.y) };
                    mma8(acc[0][ni], a[0], b);
                    mma8(acc[1][ni], a[1], b);
                }
            }
            if (c < 2) {   // stage chunk c+2 into the buffer just consumed
                __syncwarp();
                #pragma unroll
                for (int j = 0; j < 8; j++) {
                    int r = srow + 4 * j;
                    cp16(SB + (c & 1) * (32 * STG) + r * STG + su * 4,
                         gsrc + (size_t)r * 1024 + (c + 2) * 32 + su * 4);
                }
                cp_commit();
            }
        }

        // write K-partials into buffer 0 of OWN stage pair (warp-private:
        // buffer 0's last mainloop read was chunk c=2; no cross-warp alias)
        #pragma unroll
        for (int mi = 0; mi < 2; mi++)
            #pragma unroll
            for (int ni = 0; ni < 4; ni++) {
                int nc = ni * 8 + 2 * t4;
                *(float2*)&SB[(mi * 16 + g) * STG + nc] =
                    make_float2(acc[mi][ni][0], acc[mi][ni][1]);
                *(float2*)&SB[(mi * 16 + 8 + g) * STG + nc] =
                    make_float2(acc[mi][ni][2], acc[mi][ni][3]);
            }
        __syncthreads();

        // reduce 8 partials + tanh; store NEXT-STATE hd only (consumed by peers)
        float v[8], r[8];
        if (tid < 128) {
            float s[8] = {0.f,0.f,0.f,0.f,0.f,0.f,0.f,0.f};
            #pragma unroll
            for (int ww = 0; ww < 8; ww++) {
                const float* Rr = Stg + ww * STGW + er * STG + eblk * 8;
                float4 r0 = *(const float4*)&Rr[0];
                float4 r1 = *(const float4*)&Rr[4];
                s[0] += r0.x; s[1] += r0.y; s[2] += r0.z; s[3] += r0.w;
                s[4] += r1.x; s[5] += r1.y; s[6] += r1.z; s[7] += r1.w;
            }
            v[0] = tanhf(s[0] + xq0.x + bhv[0]);
            v[1] = tanhf(s[1] + xq0.y + bhv[1]);
            v[2] = tanhf(s[2] + xq0.z + bhv[2]);
            v[3] = tanhf(s[3] + xq0.w + bhv[3]);
            v[4] = tanhf(s[4] + xq1.x + bhv[4]);
            v[5] = tanhf(s[5] + xq1.y + bhv[5]);
            v[6] = tanhf(s[6] + xq1.z + bhv[6]);
            v[7] = tanhf(s[7] + xq1.w + bhv[7]);
            #pragma unroll
            for (int j = 0; j < 8; j++) r[j] = rndt(v[j]);
            *(float4*)&hd[(size_t)gr * 1024 + gcb]     = make_float4(r[0], r[4], r[1], r[5]);
            *(float4*)&hd[(size_t)gr * 1024 + gcb + 4] = make_float4(r[2], r[6], r[3], r[7]);
            __threadfence();   // make own hd stores gpu-visible (cheap: 32B->L2)
        }
        __syncthreads();       // all hd stores fenced before arrive

        if (tid == 0) atomicAdd(mybar, 1u);

        // stores nobody consumes this step + next xp prefetch: overlap poll
        if (tid < 128) {
            size_t orow = ((size_t)gr * Tt + t) * 1024 + gcb;
            *(float4*)&h_e[orow]     = make_float4(v[0], v[1], v[2], v[3]);
            *(float4*)&h_e[orow + 4] = make_float4(v[4], v[5], v[6], v[7]);
            *(float4*)&g_hr[orow]     = make_float4(r[0], r[4], r[1], r[5]);
            *(float4*)&g_hr[orow + 4] = make_float4(r[2], r[6], r[3], r[7]);
            if (t + 1 < Tt) {
                xq0 = *(const float4*)&g_xp[(size_t)((t + 1) * 128 + gr) * 1024 + gcb];
                xq1 = *(const float4*)&g_xp[(size_t)((t + 1) * 128 + gr) * 1024 + gcb + 4];
            }
        }

        if (tid == 0) {
            unsigned tgt = (unsigned)(32 * (t + 1)), vv;
            do {
                asm volatile("ld.acquire.gpu.u32 %0, [%1];" : "=r"(vv) : "l"(mybar));
            } while (vv < tgt);
        }
        __syncthreads();
    }
}

// -------- launch ---------------------------------------------------------
extern "C" void kernel_launch(void* const* d_in, const int* in_sizes, int n_in,
                              void* d_out, int out_size) {
    (void)in_sizes; (void)n_in; (void)out_size;
    const int*   x      = (const int*)d_in[0];
    const float* h_init = (const float*)d_in[1];
    const float* embed  = (const float*)d_in[2];
    const float* Wx     = (const float*)d_in[3];
    const float* bx     = (const float*)d_in[4];
    const float* Wh     = (const float*)d_in[5];
    const float* bh     = (const float*)d_in[6];
    const float* Wo     = (const float*)d_in[7];
    const float* bo     = (const float*)d_in[8];

    float* out = (float*)d_out;
    float* h_e = out;                       // [B][T][H]
    float* y_e = out + (size_t)BT * Hh;     // [B][T][V]

    const int SMEM_P = (3 * ASZ + 3 * BSZ) * 4 + 128 * 8;   // 102400
    const int SMEM_R = SMEM_RF * 4;                         // 206336

    cudaFuncSetAttribute(gemm_k<true>,  cudaFuncAttributeMaxDynamicSharedMemorySize, SMEM_P);
    cudaFuncSetAttribute(gemm_k<false>, cudaFuncAttributeMaxDynamicSharedMemorySize, SMEM_P);
    cudaFuncSetAttribute(rnn_k,         cudaFuncAttributeMaxDynamicSharedMemorySize, SMEM_R);

    void* xp_ptr = nullptr;   cudaGetSymbolAddress(&xp_ptr, g_xp);
    void* hr_ptr = nullptr;   cudaGetSymbolAddress(&hr_ptr, g_hr);
    void* emb_ptr = nullptr;  cudaGetSymbolAddress(&emb_ptr, g_embr);
    void* wx_ptr = nullptr;   cudaGetSymbolAddress(&wx_ptr, g_Wxr);
    void* wo_ptr = nullptr;   cudaGetSymbolAddress(&wo_ptr, g_Wor);

    // 1. round+permute embed/Wx/Wo; reset barriers; h_init -> g_h[0]
    prep_k<<<512, 256>>>(embed, Wx, Wo);
    init_k<<<128, 256>>>(h_init);
    // 2. xp[t][b][:] = embed_r[x[b][t]] @ Wx_r^T + bx
    gemm_k<true><<<dim3(16, 512), 256, SMEM_P>>>((const float*)emb_ptr, x,
                                                 (const float*)wx_ptr, bx, (float*)xp_ptr);
    // 3. serial recurrence -> h_e (+ rounded copies)
    rnn_k<<<128, 256, SMEM_R>>>(Wh, bh, h_e);
    // 4. y = h_r @ Wo_r^T + bo
    gemm_k<false><<<dim3(16, 512), 256, SMEM_P>>>((const float*)hr_ptr, nullptr,
                                                  (const float*)wo_ptr, bo, y_e);
}

// round 8
// speedup vs baseline: 1.8176x; 1.0531x over previous
#include <cuda_runtime.h>
#include <cstdint>
#include <math.h>

// Problem dims (fixed)
#define Bb 128
#define Tt 512
#define Hh 1024
#define BT (Bb*Tt)

// -------- device-global scratch ------------------------------------------
__device__ float g_xp[(size_t)BT * Hh];    // 256 MB input projections [T][B][H]
__device__ float g_hr[(size_t)BT * Hh];    // 256 MB rounded+permuted h [B][T][H]
__device__ float g_h[2][Bb * Hh];          // h double buffer (rounded+permuted)
__device__ float g_embr[1024 * 1024];      // rounded+permuted embed table
__device__ float g_Wxr[1024 * 1024];       // rounded+permuted Wx
__device__ float g_Wor[1024 * 1024];       // rounded+permuted Wo
__device__ unsigned int g_barA[4 * 32];    // 4 per-group counters, 128B apart

// -------- helpers --------------------------------------------------------
__device__ __forceinline__ uint32_t f2t(float x) {
    uint32_t u; asm("cvt.rna.tf32.f32 %0, %1;" : "=r"(u) : "f"(x));
    return u;
}
__device__ __forceinline__ float rndt(float x) { return __uint_as_float(f2t(x)); }
// k-pair interleave within 8-blocks: (j, j+4) -> positions (2j, 2j+1)
__device__ __forceinline__ int pig(int k) {
    int j = k & 7;
    return (k & ~7) | ((j < 4) ? (2 * j) : (2 * (j - 4) + 1));
}
__device__ __forceinline__ void cp16(float* s, const float* g) {
    uint32_t sa = (uint32_t)__cvta_generic_to_shared(s);
    asm volatile("cp.async.cg.shared.global [%0], [%1], 16;\n" :: "r"(sa), "l"(g));
}
__device__ __forceinline__ void cp_commit() { asm volatile("cp.async.commit_group;\n"); }
template<int N> __device__ __forceinline__ void cp_wait() {
    asm volatile("cp.async.wait_group %0;\n" :: "n"(N));
}
__device__ __forceinline__ void mma8(float* c, const uint32_t* a, const uint32_t* b) {
    asm volatile(
        "mma.sync.aligned.m16n8k8.row.col.f32.tf32.tf32.f32 "
        "{%0,%1,%2,%3},{%4,%5,%6,%7},{%8,%9},{%0,%1,%2,%3};"
        : "+f"(c[0]), "+f"(c[1]), "+f"(c[2]), "+f"(c[3])
        : "r"(a[0]), "r"(a[1]), "r"(a[2]), "r"(a[3]), "r"(b[0]), "r"(b[1]));
}

// -------- prologue: round+permute embed, Wx, Wo --------------------------
__global__ void prep_k(const float* __restrict__ e, const float* __restrict__ wx,
                       const float* __restrict__ wo) {
    int st = gridDim.x * blockDim.x;
    for (int i = blockIdx.x * blockDim.x + threadIdx.x; i < 1024 * 1024; i += st) {
        int r = i >> 10, k = i & 1023;
        int d = (r << 10) | pig(k);
        g_embr[d] = rndt(e[i]);
        g_Wxr[d]  = rndt(wx[i]);
        g_Wor[d]  = rndt(wo[i]);
    }
}

__global__ void init_k(const float* __restrict__ h0) {
    int i = blockIdx.x * blockDim.x + threadIdx.x;
    if (i < 128) g_barA[i] = 0u;
    for (int j = i; j < Bb * Hh; j += gridDim.x * blockDim.x) {
        int r = j >> 10, k = j & 1023;
        g_h[0][(r << 10) | pig(k)] = rndt(h0[j]);
    }
}

// -------- phase GEMM: C[m][n] = sum_k A[m][k]*W[n][k] + bias[n] ----------
// Tile 128x64xK32, 256 threads = 8 warps (4M x 2N) of 32x32.
// 3-stage cp.async ring, prefetch depth 2.
#define PS 44
#define ASZ 5632
#define BSZ 2816

__device__ __forceinline__ void stage_p(const float* const* rp, const float* __restrict__ W,
                                        int n0, int k0, float* As, float* Bs, int tid) {
    #pragma unroll
    for (int j = 0; j < 4; j++) {
        int c = j * 256 + tid; int r = c >> 3, o = c & 7;
        cp16(As + r * PS + o * 4, rp[r] + k0 + o * 4);
    }
    #pragma unroll
    for (int j = 0; j < 2; j++) {
        int c = j * 256 + tid; int r = c >> 3, o = c & 7;
        cp16(Bs + r * PS + o * 4, W + (size_t)(n0 + r) * 1024 + k0 + o * 4);
    }
}

template<bool GATHER>
__global__ __launch_bounds__(256, 2) void gemm_k(const float* __restrict__ Ab,
                                                 const int* __restrict__ tok,
                                                 const float* __restrict__ W,
                                                 const float* __restrict__ bias,
                                                 float* __restrict__ C) {
    extern __shared__ float sm[];
    float* As = sm;
    float* Bs = sm + 3 * ASZ;
    const float** rp = (const float**)(sm + 3 * ASZ + 3 * BSZ);

    const int tid = threadIdx.x;
    if (tid < 128) {
        if (GATHER) rp[tid] = Ab + (size_t)tok[tid * Tt + blockIdx.y] * 1024;
        else        rp[tid] = Ab + ((size_t)blockIdx.y * 128 + tid) * 1024;
    }
    __syncthreads();

    const int n0 = blockIdx.x * 64;
    const int lane = tid & 31, w = tid >> 5;
    const int g = lane >> 2, t4 = lane & 3;
    const int wm = (w >> 1) * 32, wn = (w & 1) * 32;

    float acc[2][4][4];
    #pragma unroll
    for (int a = 0; a < 2; a++)
        #pragma unroll
        for (int b = 0; b < 4; b++)
            #pragma unroll
            for (int c = 0; c < 4; c++) acc[a][b][c] = 0.f;

    stage_p(rp, W, n0, 0, As, Bs, tid);              cp_commit();
    stage_p(rp, W, n0, 32, As + ASZ, Bs + BSZ, tid); cp_commit();

    int buf = 0;
    for (int ks = 0; ks < 32; ks++) {
        if (ks < 30) cp_wait<1>(); else cp_wait<0>();
        __syncthreads();
        if (ks < 30) {
            int nb = buf + 2; if (nb >= 3) nb -= 3;
            stage_p(rp, W, n0, (ks + 2) * 32, As + nb * ASZ, Bs + nb * BSZ, tid);
            cp_commit();
        }
        const float* A_ = As + buf * ASZ;
        const float* B_ = Bs + buf * BSZ;
        #pragma unroll
        for (int kk = 0; kk < 32; kk += 8) {
            uint32_t a[2][4];
            #pragma unroll
            for (int mi = 0; mi < 2; mi++) {
                float2 p0 = *(const float2*)&A_[(wm + mi * 16 + g) * PS + kk + 2 * t4];
                float2 p1 = *(const float2*)&A_[(wm + mi * 16 + 8 + g) * PS + kk + 2 * t4];
                a[mi][0] = __float_as_uint(p0.x); a[mi][1] = __float_as_uint(p1.x);
                a[mi][2] = __float_as_uint(p0.y); a[mi][3] = __float_as_uint(p1.y);
            }
            #pragma unroll
            for (int ni = 0; ni < 4; ni++) {
                float2 q = *(const float2*)&B_[(wn + ni * 8 + g) * PS + kk + 2 * t4];
                uint32_t b[2] = { __float_as_uint(q.x), __float_as_uint(q.y) };
                mma8(acc[0][ni], a[0], b);
                mma8(acc[1][ni], a[1], b);
            }
        }
        buf++; if (buf >= 3) buf -= 3;
    }

    const int m0 = blockIdx.y * 128;
    #pragma unroll
    for (int ni = 0; ni < 4; ni++) {
        int nc = n0 + wn + ni * 8 + 2 * t4;
        float b0 = bias[nc], b1 = bias[nc + 1];
        #pragma unroll
        for (int mi = 0; mi < 2; mi++) {
            int r0 = m0 + wm + mi * 16 + g;
            *(float2*)&C[(size_t)r0 * 1024 + nc] =
                make_float2(acc[mi][ni][0] + b0, acc[mi][ni][1] + b1);
            *(float2*)&C[(size_t)(r0 + 8) * 1024 + nc] =
                make_float2(acc[mi][ni][2] + b0, acc[mi][ni][3] + b1);
        }
    }
}

// -------- persistent recurrence kernel (v5) ------------------------------
// 128 CTAs = 4 independent M-groups x 32 N-CTAs, 256 thr (8 warps).
// Wh lives in REGISTERS (64 mma B-frags = 128 regs/thread, rounded RNA at
// load -> same values as the old smem copy, bit-identical math). All 132 KB
// of freed smem goes to h staging: 4 chunk buffers per warp, all 4 chunks
// issued right after the barrier (one L2 round trip per step, drained with
// cp_wait<3..0> overlapped with mma). Partials reuse chunk-0 buffer.
#define STG 36              // stage row stride (floats)
#define CHB (32 * STG)      // one chunk buffer = 1152 floats
#define CHW (4 * CHB)       // per-warp: 4 buffers = 4608 floats
#define SMEM_RF (8 * CHW)   // 36864 floats = 147456 B

__global__ __launch_bounds__(256, 1) void rnn_k(const float* __restrict__ Wh,
                                                const float* __restrict__ bh,
                                                float* __restrict__ h_e) {
    extern __shared__ float sm[];
    float* Stg = sm;                       // 8 warps x 4 x (32x36)

    const int tid = threadIdx.x;
    const int nq = blockIdx.x & 31, mq = blockIdx.x >> 5;
    const int nb = nq * 32, mb = mq * 32;
    unsigned int* mybar = &g_barA[mq * 32];

    const int lane = tid & 31, w = tid >> 5;
    const int g = lane >> 2, t4 = lane & 3;
    const int kb = w * 128;
    float* SB = Stg + w * CHW;
    const int srow = lane >> 3, su = lane & 7;

    // ---- load Wh B-fragments into registers (rounded RNA; once) ----
    uint32_t bfr[4][16][2];
    #pragma unroll
    for (int ni = 0; ni < 4; ni++) {
        const float* Wrow = Wh + (size_t)(nb + ni * 8 + g) * 1024 + kb + t4;
        #pragma unroll
        for (int kf = 0; kf < 16; kf++) {
            bfr[ni][kf][0] = f2t(Wrow[kf * 8]);
            bfr[ni][kf][1] = f2t(Wrow[kf * 8 + 4]);
        }
    }

    // epilogue mapping (tid<128): row er, cols [gcb, gcb+8)
    const int er = tid & 31, eblk = tid >> 5;
    const int gr = mb + er, gcb = nb + eblk * 8;
    float bhv[8];
    float4 xq0, xq1;
    if (tid < 128) {
        float4 q0 = *(const float4*)&bh[gcb];
        float4 q1 = *(const float4*)&bh[gcb + 4];
        bhv[0]=q0.x; bhv[1]=q0.y; bhv[2]=q0.z; bhv[3]=q0.w;
        bhv[4]=q1.x; bhv[5]=q1.y; bhv[6]=q1.z; bhv[7]=q1.w;
        xq0 = *(const float4*)&g_xp[(size_t)gr * 1024 + gcb];
        xq1 = *(const float4*)&g_xp[(size_t)gr * 1024 + gcb + 4];
    }
    __syncthreads();

    for (int t = 0; t < Tt; t++) {
        const float* hs = g_h[t & 1];
        float* hd = g_h[(t + 1) & 1];
        const float* gsrc = hs + (size_t)mb * 1024 + kb;

        float acc[2][4][4];
        #pragma unroll
        for (int a = 0; a < 2; a++)
            #pragma unroll
            for (int b = 0; b < 4; b++)
                #pragma unroll
                for (int c = 0; c < 4; c++) acc[a][b][c] = 0.f;

        // stage ALL 4 chunks now (one L2 round trip, 4 commit groups)
        #pragma unroll
        for (int cc = 0; cc < 4; cc++) {
            #pragma unroll
            for (int j = 0; j < 8; j++) {
                int r = srow + 4 * j;
                cp16(SB + cc * CHB + r * STG + su * 4,
                     gsrc + (size_t)r * 1024 + cc * 32 + su * 4);
            }
            cp_commit();
        }

        #pragma unroll
        for (int c = 0; c < 4; c++) {
            if (c == 0) cp_wait<3>();
            else if (c == 1) cp_wait<2>();
            else if (c == 2) cp_wait<1>();
            else cp_wait<0>();
            __syncwarp();
            const float* B_ = SB + c * CHB;
            #pragma unroll
            for (int kf = 0; kf < 4; kf++) {
                uint32_t a[2][4];
                #pragma unroll
                for (int mi = 0; mi < 2; mi++) {
                    float2 p0 = *(const float2*)&B_[(mi * 16 + g) * STG + kf * 8 + 2 * t4];
                    float2 p1 = *(const float2*)&B_[(mi * 16 + 8 + g) * STG + kf * 8 + 2 * t4];
                    a[mi][0] = __float_as_uint(p0.x); a[mi][1] = __float_as_uint(p1.x);
                    a[mi][2] = __float_as_uint(p0.y); a[mi][3] = __float_as_uint(p1.y);
                }
                #pragma unroll
                for (int ni = 0; ni < 4; ni++) {
                    mma8(acc[0][ni], a[0], bfr[ni][c * 4 + kf]);
                    mma8(acc[1][ni], a[1], bfr[ni][c * 4 + kf]);
                }
            }
        }

        // K-partials into own chunk-0 buffer (first consumed; warp-private)
        #pragma unroll
        for (int mi = 0; mi < 2; mi++)
            #pragma unroll
            for (int ni = 0; ni < 4; ni++) {
                int nc = ni * 8 + 2 * t4;
                *(float2*)&SB[(mi * 16 + g) * STG + nc] =
                    make_float2(acc[mi][ni][0], acc[mi][ni][1]);
                *(float2*)&SB[(mi * 16 + 8 + g) * STG + nc] =
                    make_float2(acc[mi][ni][2], acc[mi][ni][3]);
            }
        __syncthreads();

        // reduce 8 partials + tanh; store NEXT-STATE hd only
        float v[8], r[8];
        if (tid < 128) {
            float s[8] = {0.f,0.f,0.f,0.f,0.f,0.f,0.f,0.f};
            #pragma unroll
            for (int ww = 0; ww < 8; ww++) {
                const float* Rr = Stg + ww * CHW + er * STG + eblk * 8;
                float4 r0 = *(const float4*)&Rr[0];
                float4 r1 = *(const float4*)&Rr[4];
                s[0] += r0.x; s[1] += r0.y; s[2] += r0.z; s[3] += r0.w;
                s[4] += r1.x; s[5] += r1.y; s[6] += r1.z; s[7] += r1.w;
            }
            v[0] = tanhf(s[0] + xq0.x + bhv[0]);
            v[1] = tanhf(s[1] + xq0.y + bhv[1]);
            v[2] = tanhf(s[2] + xq0.z + bhv[2]);
            v[3] = tanhf(s[3] + xq0.w + bhv[3]);
            v[4] = tanhf(s[4] + xq1.x + bhv[4]);
            v[5] = tanhf(s[5] + xq1.y + bhv[5]);
            v[6] = tanhf(s[6] + xq1.z + bhv[6]);
            v[7] = tanhf(s[7] + xq1.w + bhv[7]);
            #pragma unroll
            for (int j = 0; j < 8; j++) r[j] = rndt(v[j]);
            *(float4*)&hd[(size_t)gr * 1024 + gcb]     = make_float4(r[0], r[4], r[1], r[5]);
            *(float4*)&hd[(size_t)gr * 1024 + gcb + 4] = make_float4(r[2], r[6], r[3], r[7]);
            __threadfence();   // own hd stores gpu-visible (cheap: 32B->L2)
        }
        __syncthreads();       // all hd stores fenced before arrive

        if (tid == 0) atomicAdd(mybar, 1u);

        // stores nobody consumes this step + next xp prefetch: overlap poll
        if (tid < 128) {
            size_t orow = ((size_t)gr * Tt + t) * 1024 + gcb;
            *(float4*)&h_e[orow]     = make_float4(v[0], v[1], v[2], v[3]);
            *(float4*)&h_e[orow + 4] = make_float4(v[4], v[5], v[6], v[7]);
            *(float4*)&g_hr[orow]     = make_float4(r[0], r[4], r[1], r[5]);
            *(float4*)&g_hr[orow + 4] = make_float4(r[2], r[6], r[3], r[7]);
            if (t + 1 < Tt) {
                xq0 = *(const float4*)&g_xp[(size_t)((t + 1) * 128 + gr) * 1024 + gcb];
                xq1 = *(const float4*)&g_xp[(size_t)((t + 1) * 128 + gr) * 1024 + gcb + 4];
            }
        }

        if (tid == 0) {
            unsigned tgt = (unsigned)(32 * (t + 1)), vv;
            do {
                asm volatile("ld.acquire.gpu.u32 %0, [%1];" : "=r"(vv) : "l"(mybar));
            } while (vv < tgt);
        }
        __syncthreads();
    }
}

// -------- launch ---------------------------------------------------------
extern "C" void kernel_launch(void* const* d_in, const int* in_sizes, int n_in,
                              void* d_out, int out_size) {
    (void)in_sizes; (void)n_in; (void)out_size;
    const int*   x      = (const int*)d_in[0];
    const float* h_init = (const float*)d_in[1];
    const float* embed  = (const float*)d_in[2];
    const float* Wx     = (const float*)d_in[3];
    const float* bx     = (const float*)d_in[4];
    const float* Wh     = (const float*)d_in[5];
    const float* bh     = (const float*)d_in[6];
    const float* Wo     = (const float*)d_in[7];
    const float* bo     = (const float*)d_in[8];

    float* out = (float*)d_out;
    float* h_e = out;                       // [B][T][H]
    float* y_e = out + (size_t)BT * Hh;     // [B][T][V]

    const int SMEM_P = (3 * ASZ + 3 * BSZ) * 4 + 128 * 8;   // 102400
    const int SMEM_R = SMEM_RF * 4;                         // 147456

    cudaFuncSetAttribute(gemm_k<true>,  cudaFuncAttributeMaxDynamicSharedMemorySize, SMEM_P);
    cudaFuncSetAttribute(gemm_k<false>, cudaFuncAttributeMaxDynamicSharedMemorySize, SMEM_P);
    cudaFuncSetAttribute(rnn_k,         cudaFuncAttributeMaxDynamicSharedMemorySize, SMEM_R);

    void* xp_ptr = nullptr;   cudaGetSymbolAddress(&xp_ptr, g_xp);
    void* hr_ptr = nullptr;   cudaGetSymbolAddress(&hr_ptr, g_hr);
    void* emb_ptr = nullptr;  cudaGetSymbolAddress(&emb_ptr, g_embr);
    void* wx_ptr = nullptr;   cudaGetSymbolAddress(&wx_ptr, g_Wxr);
    void* wo_ptr = nullptr;   cudaGetSymbolAddress(&wo_ptr, g_Wor);

    // 1. round+permute embed/Wx/Wo; reset barriers; h_init -> g_h[0]
    prep_k<<<512, 256>>>(embed, Wx, Wo);
    init_k<<<128, 256>>>(h_init);
    // 2. xp[t][b][:] = embed_r[x[b][t]] @ Wx_r^T + bx
    gemm_k<true><<<dim3(16, 512), 256, SMEM_P>>>((const float*)emb_ptr, x,
                                                 (const float*)wx_ptr, bx, (float*)xp_ptr);
    // 3. serial recurrence -> h_e (+ rounded copies)
    rnn_k<<<128, 256, SMEM_R>>>(Wh, bh, h_e);
    // 4. y = h_r @ Wo_r^T + bo
    gemm_k<false><<<dim3(16, 512), 256, SMEM_P>>>((const float*)hr_ptr, nullptr,
                                                  (const float*)wo_ptr, bo, y_e);
}

// round 9
// speedup vs baseline: 1.9804x; 1.0895x over previous
#include <cuda_runtime.h>
#include <cstdint>
#include <math.h>

// Problem dims (fixed)
#define Bb 128
#define Tt 512
#define Hh 1024
#define BT (Bb*Tt)

// -------- device-global scratch ------------------------------------------
__device__ float g_xp[(size_t)BT * Hh];    // 256 MB input projections [T][B][H]
__device__ float g_hr[(size_t)BT * Hh];    // 256 MB rounded+permuted h [B][T][H]
__device__ float g_h[2][Bb * Hh];          // h double buffer (rounded+permuted)
__device__ float g_embr[1024 * 1024];      // rounded+permuted embed table
__device__ float g_Wxr[1024 * 1024];       // rounded+permuted Wx
__device__ float g_Wor[1024 * 1024];       // rounded+permuted Wo
__device__ unsigned int g_barA[4 * 32];    // 4 per-group counters, 128B apart

// -------- helpers --------------------------------------------------------
__device__ __forceinline__ uint32_t f2t(float x) {
    uint32_t u; asm("cvt.rna.tf32.f32 %0, %1;" : "=r"(u) : "f"(x));
    return u;
}
__device__ __forceinline__ float rndt(float x) { return __uint_as_float(f2t(x)); }
// k-pair interleave within 8-blocks: (j, j+4) -> positions (2j, 2j+1)
__device__ __forceinline__ int pig(int k) {
    int j = k & 7;
    return (k & ~7) | ((j < 4) ? (2 * j) : (2 * (j - 4) + 1));
}
__device__ __forceinline__ void cp16(float* s, const float* g) {
    uint32_t sa = (uint32_t)__cvta_generic_to_shared(s);
    asm volatile("cp.async.cg.shared.global [%0], [%1], 16;\n" :: "r"(sa), "l"(g));
}
__device__ __forceinline__ void cp_commit() { asm volatile("cp.async.commit_group;\n"); }
template<int N> __device__ __forceinline__ void cp_wait() {
    asm volatile("cp.async.wait_group %0;\n" :: "n"(N));
}
__device__ __forceinline__ void mma8(float* c, const uint32_t* a, const uint32_t* b) {
    asm volatile(
        "mma.sync.aligned.m16n8k8.row.col.f32.tf32.tf32.f32 "
        "{%0,%1,%2,%3},{%4,%5,%6,%7},{%8,%9},{%0,%1,%2,%3};"
        : "+f"(c[0]), "+f"(c[1]), "+f"(c[2]), "+f"(c[3])
        : "r"(a[0]), "r"(a[1]), "r"(a[2]), "r"(a[3]), "r"(b[0]), "r"(b[1]));
}

// -------- prologue: round+permute embed, Wx, Wo --------------------------
__global__ void prep_k(const float* __restrict__ e, const float* __restrict__ wx,
                       const float* __restrict__ wo) {
    int st = gridDim.x * blockDim.x;
    for (int i = blockIdx.x * blockDim.x + threadIdx.x; i < 1024 * 1024; i += st) {
        int r = i >> 10, k = i & 1023;
        int d = (r << 10) | pig(k);
        g_embr[d] = rndt(e[i]);
        g_Wxr[d]  = rndt(wx[i]);
        g_Wor[d]  = rndt(wo[i]);
    }
}

__global__ void init_k(const float* __restrict__ h0) {
    int i = blockIdx.x * blockDim.x + threadIdx.x;
    if (i < 128) g_barA[i] = 0u;
    for (int j = i; j < Bb * Hh; j += gridDim.x * blockDim.x) {
        int r = j >> 10, k = j & 1023;
        g_h[0][(r << 10) | pig(k)] = rndt(h0[j]);
    }
}

// -------- phase GEMM: C[m][n] = sum_k A[m][k]*W[n][k] + bias[n] ----------
// Tile 128(M) x 128(N) x 32(K), 256 threads = 8 warps (2M x 4N), warp 64x32.
// 3-stage cp.async ring, prefetch depth 2.
#define PS 44
#define TSZ 5632   // 128 rows x 44 per stage (A or B)

__device__ __forceinline__ void stage_p(const float* const* rp, const float* __restrict__ W,
                                        int n0, int k0, float* As, float* Bs, int tid) {
    #pragma unroll
    for (int j = 0; j < 4; j++) {                 // A: 128 rows x 32 floats
        int c = j * 256 + tid; int r = c >> 3, o = c & 7;
        cp16(As + r * PS + o * 4, rp[r] + k0 + o * 4);
    }
    #pragma unroll
    for (int j = 0; j < 4; j++) {                 // B: 128 rows x 32 floats
        int c = j * 256 + tid; int r = c >> 3, o = c & 7;
        cp16(Bs + r * PS + o * 4, W + (size_t)(n0 + r) * 1024 + k0 + o * 4);
    }
}

template<bool GATHER>
__global__ __launch_bounds__(256, 1) void gemm_k(const float* __restrict__ Ab,
                                                 const int* __restrict__ tok,
                                                 const float* __restrict__ W,
                                                 const float* __restrict__ bias,
                                                 float* __restrict__ C) {
    extern __shared__ float sm[];
    float* As = sm;                        // 3 x 5632
    float* Bs = sm + 3 * TSZ;              // 3 x 5632
    const float** rp = (const float**)(sm + 6 * TSZ);   // 128 ptrs

    const int tid = threadIdx.x;
    if (tid < 128) {
        if (GATHER) rp[tid] = Ab + (size_t)tok[tid * Tt + blockIdx.y] * 1024;
        else        rp[tid] = Ab + ((size_t)blockIdx.y * 128 + tid) * 1024;
    }
    __syncthreads();

    const int n0 = blockIdx.x * 128;
    const int lane = tid & 31, w = tid >> 5;
    const int g = lane >> 2, t4 = lane & 3;
    const int wm = (w >> 2) * 64, wn = (w & 3) * 32;

    float acc[4][4][4];
    #pragma unroll
    for (int a = 0; a < 4; a++)
        #pragma unroll
        for (int b = 0; b < 4; b++)
            #pragma unroll
            for (int c = 0; c < 4; c++) acc[a][b][c] = 0.f;

    stage_p(rp, W, n0, 0, As, Bs, tid);              cp_commit();
    stage_p(rp, W, n0, 32, As + TSZ, Bs + TSZ, tid); cp_commit();

    int buf = 0;
    for (int ks = 0; ks < 32; ks++) {
        if (ks < 30) cp_wait<1>(); else cp_wait<0>();
        __syncthreads();
        if (ks < 30) {
            int nb = buf + 2; if (nb >= 3) nb -= 3;
            stage_p(rp, W, n0, (ks + 2) * 32, As + nb * TSZ, Bs + nb * TSZ, tid);
            cp_commit();
        }
        const float* A_ = As + buf * TSZ;
        const float* B_ = Bs + buf * TSZ;
        #pragma unroll
        for (int kk = 0; kk < 32; kk += 8) {
            uint32_t a[4][4];
            #pragma unroll
            for (int mi = 0; mi < 4; mi++) {
                float2 p0 = *(const float2*)&A_[(wm + mi * 16 + g) * PS + kk + 2 * t4];
                float2 p1 = *(const float2*)&A_[(wm + mi * 16 + 8 + g) * PS + kk + 2 * t4];
                a[mi][0] = __float_as_uint(p0.x); a[mi][1] = __float_as_uint(p1.x);
                a[mi][2] = __float_as_uint(p0.y); a[mi][3] = __float_as_uint(p1.y);
            }
            #pragma unroll
            for (int ni = 0; ni < 4; ni++) {
                float2 q = *(const float2*)&B_[(wn + ni * 8 + g) * PS + kk + 2 * t4];
                uint32_t b[2] = { __float_as_uint(q.x), __float_as_uint(q.y) };
                #pragma unroll
                for (int mi = 0; mi < 4; mi++)
                    mma8(acc[mi][ni], a[mi], b);
            }
        }
        buf++; if (buf >= 3) buf -= 3;
    }

    const int m0 = blockIdx.y * 128;
    #pragma unroll
    for (int ni = 0; ni < 4; ni++) {
        int nc = n0 + wn + ni * 8 + 2 * t4;
        float b0 = bias[nc], b1 = bias[nc + 1];
        #pragma unroll
        for (int mi = 0; mi < 4; mi++) {
            int r0 = m0 + wm + mi * 16 + g;
            *(float2*)&C[(size_t)r0 * 1024 + nc] =
                make_float2(acc[mi][ni][0] + b0, acc[mi][ni][1] + b1);
            *(float2*)&C[(size_t)(r0 + 8) * 1024 + nc] =
                make_float2(acc[mi][ni][2] + b0, acc[mi][ni][3] + b1);
        }
    }
}

// -------- persistent recurrence kernel (v6) ------------------------------
// 128 CTAs = 4 independent M-groups x 32 N-CTAs, 256 thr (8 warps).
// Wh in registers; one-shot 4-chunk h staging; partials in own chunk-0.
// Cross-CTA sync = cooperative-groups pattern: st hd -> bar.sync (CTA-scope
// fence) -> tid0 red.release.gpu -> consumer ld.acquire. NO per-thread
// __threadfence (removes the in-flight-DRAM-store drain from the chain).
#define STG 36              // stage row stride (floats)
#define CHB (32 * STG)      // one chunk buffer = 1152 floats
#define CHW (4 * CHB)       // per-warp: 4 buffers = 4608 floats
#define SMEM_RF (8 * CHW)   // 36864 floats = 147456 B

__global__ __launch_bounds__(256, 1) void rnn_k(const float* __restrict__ Wh,
                                                const float* __restrict__ bh,
                                                float* __restrict__ h_e) {
    extern __shared__ float sm[];
    float* Stg = sm;                       // 8 warps x 4 x (32x36)

    const int tid = threadIdx.x;
    const int nq = blockIdx.x & 31, mq = blockIdx.x >> 5;
    const int nb = nq * 32, mb = mq * 32;
    unsigned int* mybar = &g_barA[mq * 32];

    const int lane = tid & 31, w = tid >> 5;
    const int g = lane >> 2, t4 = lane & 3;
    const int kb = w * 128;
    float* SB = Stg + w * CHW;
    const int srow = lane >> 3, su = lane & 7;

    // ---- load Wh B-fragments into registers (rounded RNA; once) ----
    uint32_t bfr[4][16][2];
    #pragma unroll
    for (int ni = 0; ni < 4; ni++) {
        const float* Wrow = Wh + (size_t)(nb + ni * 8 + g) * 1024 + kb + t4;
        #pragma unroll
        for (int kf = 0; kf < 16; kf++) {
            bfr[ni][kf][0] = f2t(Wrow[kf * 8]);
            bfr[ni][kf][1] = f2t(Wrow[kf * 8 + 4]);
        }
    }

    // epilogue mapping (tid<128): row er, cols [gcb, gcb+8)
    const int er = tid & 31, eblk = tid >> 5;
    const int gr = mb + er, gcb = nb + eblk * 8;
    float bhv[8];
    float4 xq0, xq1;
    if (tid < 128) {
        float4 q0 = *(const float4*)&bh[gcb];
        float4 q1 = *(const float4*)&bh[gcb + 4];
        bhv[0]=q0.x; bhv[1]=q0.y; bhv[2]=q0.z; bhv[3]=q0.w;
        bhv[4]=q1.x; bhv[5]=q1.y; bhv[6]=q1.z; bhv[7]=q1.w;
        xq0 = *(const float4*)&g_xp[(size_t)gr * 1024 + gcb];
        xq1 = *(const float4*)&g_xp[(size_t)gr * 1024 + gcb + 4];
    }
    __syncthreads();

    for (int t = 0; t < Tt; t++) {
        const float* hs = g_h[t & 1];
        float* hd = g_h[(t + 1) & 1];
        const float* gsrc = hs + (size_t)mb * 1024 + kb;

        float acc[2][4][4];
        #pragma unroll
        for (int a = 0; a < 2; a++)
            #pragma unroll
            for (int b = 0; b < 4; b++)
                #pragma unroll
                for (int c = 0; c < 4; c++) acc[a][b][c] = 0.f;

        // stage ALL 4 chunks now (one L2 round trip, 4 commit groups)
        #pragma unroll
        for (int cc = 0; cc < 4; cc++) {
            #pragma unroll
            for (int j = 0; j < 8; j++) {
                int r = srow + 4 * j;
                cp16(SB + cc * CHB + r * STG + su * 4,
                     gsrc + (size_t)r * 1024 + cc * 32 + su * 4);
            }
            cp_commit();
        }

        #pragma unroll
        for (int c = 0; c < 4; c++) {
            if (c == 0) cp_wait<3>();
            else if (c == 1) cp_wait<2>();
            else if (c == 2) cp_wait<1>();
            else cp_wait<0>();
            __syncwarp();
            const float* B_ = SB + c * CHB;
            #pragma unroll
            for (int kf = 0; kf < 4; kf++) {
                uint32_t a[2][4];
                #pragma unroll
                for (int mi = 0; mi < 2; mi++) {
                    float2 p0 = *(const float2*)&B_[(mi * 16 + g) * STG + kf * 8 + 2 * t4];
                    float2 p1 = *(const float2*)&B_[(mi * 16 + 8 + g) * STG + kf * 8 + 2 * t4];
                    a[mi][0] = __float_as_uint(p0.x); a[mi][1] = __float_as_uint(p1.x);
                    a[mi][2] = __float_as_uint(p0.y); a[mi][3] = __float_as_uint(p1.y);
                }
                #pragma unroll
                for (int ni = 0; ni < 4; ni++) {
                    mma8(acc[0][ni], a[0], bfr[ni][c * 4 + kf]);
                    mma8(acc[1][ni], a[1], bfr[ni][c * 4 + kf]);
                }
            }
        }

        // K-partials into own chunk-0 buffer (first consumed; warp-private)
        #pragma unroll
        for (int mi = 0; mi < 2; mi++)
            #pragma unroll
            for (int ni = 0; ni < 4; ni++) {
                int nc = ni * 8 + 2 * t4;
                *(float2*)&SB[(mi * 16 + g) * STG + nc] =
                    make_float2(acc[mi][ni][0], acc[mi][ni][1]);
                *(float2*)&SB[(mi * 16 + 8 + g) * STG + nc] =
                    make_float2(acc[mi][ni][2], acc[mi][ni][3]);
            }
        __syncthreads();

        // reduce 8 partials + tanh; store NEXT-STATE hd only
        float v[8], r[8];
        if (tid < 128) {
            float s[8] = {0.f,0.f,0.f,0.f,0.f,0.f,0.f,0.f};
            #pragma unroll
            for (int ww = 0; ww < 8; ww++) {
                const float* Rr = Stg + ww * CHW + er * STG + eblk * 8;
                float4 r0 = *(const float4*)&Rr[0];
                float4 r1 = *(const float4*)&Rr[4];
                s[0] += r0.x; s[1] += r0.y; s[2] += r0.z; s[3] += r0.w;
                s[4] += r1.x; s[5] += r1.y; s[6] += r1.z; s[7] += r1.w;
            }
            v[0] = tanhf(s[0] + xq0.x + bhv[0]);
            v[1] = tanhf(s[1] + xq0.y + bhv[1]);
            v[2] = tanhf(s[2] + xq0.z + bhv[2]);
            v[3] = tanhf(s[3] + xq0.w + bhv[3]);
            v[4] = tanhf(s[4] + xq1.x + bhv[4]);
            v[5] = tanhf(s[5] + xq1.y + bhv[5]);
            v[6] = tanhf(s[6] + xq1.z + bhv[6]);
            v[7] = tanhf(s[7] + xq1.w + bhv[7]);
            #pragma unroll
            for (int j = 0; j < 8; j++) r[j] = rndt(v[j]);
            *(float4*)&hd[(size_t)gr * 1024 + gcb]     = make_float4(r[0], r[4], r[1], r[5]);
            *(float4*)&hd[(size_t)gr * 1024 + gcb + 4] = make_float4(r[2], r[6], r[3], r[7]);
        }
        __syncthreads();   // CTA-scope fence: all hd stores happen-before tid0

        if (tid == 0)
            asm volatile("red.release.gpu.global.add.u32 [%0], %1;"
                         :: "l"(mybar), "r"(1u) : "memory");

        // stores nobody consumes this step + next xp prefetch: overlap poll
        if (tid < 128) {
            size_t orow = ((size_t)gr * Tt + t) * 1024 + gcb;
            *(float4*)&h_e[orow]     = make_float4(v[0], v[1], v[2], v[3]);
            *(float4*)&h_e[orow + 4] = make_float4(v[4], v[5], v[6], v[7]);
            *(float4*)&g_hr[orow]     = make_float4(r[0], r[4], r[1], r[5]);
            *(float4*)&g_hr[orow + 4] = make_float4(r[2], r[6], r[3], r[7]);
            if (t + 1 < Tt) {
                xq0 = *(const float4*)&g_xp[(size_t)((t + 1) * 128 + gr) * 1024 + gcb];
                xq1 = *(const float4*)&g_xp[(size_t)((t + 1) * 128 + gr) * 1024 + gcb + 4];
            }
        }

        if (tid == 0) {
            unsigned tgt = (unsigned)(32 * (t + 1)), vv;
            do {
                asm volatile("ld.acquire.gpu.u32 %0, [%1];" : "=r"(vv) : "l"(mybar));
            } while (vv < tgt);
        }
        __syncthreads();
    }
}

// -------- launch ---------------------------------------------------------
extern "C" void kernel_launch(void* const* d_in, const int* in_sizes, int n_in,
                              void* d_out, int out_size) {
    (void)in_sizes; (void)n_in; (void)out_size;
    const int*   x      = (const int*)d_in[0];
    const float* h_init = (const float*)d_in[1];
    const float* embed  = (const float*)d_in[2];
    const float* Wx     = (const float*)d_in[3];
    const float* bx     = (const float*)d_in[4];
    const float* Wh     = (const float*)d_in[5];
    const float* bh     = (const float*)d_in[6];
    const float* Wo     = (const float*)d_in[7];
    const float* bo     = (const float*)d_in[8];

    float* out = (float*)d_out;
    float* h_e = out;                       // [B][T][H]
    float* y_e = out + (size_t)BT * Hh;     // [B][T][V]

    const int SMEM_P = 6 * TSZ * 4 + 128 * 8;               // 135168 + 1024 = 136192
    const int SMEM_R = SMEM_RF * 4;                         // 147456

    cudaFuncSetAttribute(gemm_k<true>,  cudaFuncAttributeMaxDynamicSharedMemorySize, SMEM_P);
    cudaFuncSetAttribute(gemm_k<false>, cudaFuncAttributeMaxDynamicSharedMemorySize, SMEM_P);
    cudaFuncSetAttribute(rnn_k,         cudaFuncAttributeMaxDynamicSharedMemorySize, SMEM_R);

    void* xp_ptr = nullptr;   cudaGetSymbolAddress(&xp_ptr, g_xp);
    void* hr_ptr = nullptr;   cudaGetSymbolAddress(&hr_ptr, g_hr);
    void* emb_ptr = nullptr;  cudaGetSymbolAddress(&emb_ptr, g_embr);
    void* wx_ptr = nullptr;   cudaGetSymbolAddress(&wx_ptr, g_Wxr);
    void* wo_ptr = nullptr;   cudaGetSymbolAddress(&wo_ptr, g_Wor);

    // 1. round+permute embed/Wx/Wo; reset barriers; h_init -> g_h[0]
    prep_k<<<512, 256>>>(embed, Wx, Wo);
    init_k<<<128, 256>>>(h_init);
    // 2. xp[t][b][:] = embed_r[x[b][t]] @ Wx_r^T + bx
    gemm_k<true><<<dim3(8, 512), 256, SMEM_P>>>((const float*)emb_ptr, x,
                                                (const float*)wx_ptr, bx, (float*)xp_ptr);
    // 3. serial recurrence -> h_e (+ rounded copies)
    rnn_k<<<128, 256, SMEM_R>>>(Wh, bh, h_e);
    // 4. y = h_r @ Wo_r^T + bo
    gemm_k<false><<<dim3(8, 512), 256, SMEM_P>>>((const float*)hr_ptr, nullptr,
                                                 (const float*)wo_ptr, bo, y_e);
}

// round 10
// speedup vs baseline: 2.0947x; 1.0577x over previous
#include <cuda_runtime.h>
#include <cstdint>
#include <math.h>

// Problem dims (fixed)
#define Bb 128
#define Tt 512
#define Hh 1024
#define BT (Bb*Tt)

// -------- device-global scratch ------------------------------------------
__device__ float g_xp[(size_t)BT * Hh];    // 256 MB input projections [T][B][H]
__device__ float g_hr[(size_t)BT * Hh];    // 256 MB rounded+permuted h [B][T][H]
__device__ float g_h[2][Bb * Hh];          // h double buffer (rounded+permuted)
__device__ float g_embr[1024 * 1024];      // rounded+permuted embed table
__device__ float g_Wxr[1024 * 1024];       // rounded+permuted Wx
__device__ float g_Wor[1024 * 1024];       // rounded+permuted Wo
__device__ unsigned int g_flag[128 * 32];  // per-CTA publish counters, 128B apart

// -------- helpers --------------------------------------------------------
__device__ __forceinline__ uint32_t f2t(float x) {
    uint32_t u; asm("cvt.rna.tf32.f32 %0, %1;" : "=r"(u) : "f"(x));
    return u;
}
__device__ __forceinline__ float rndt(float x) { return __uint_as_float(f2t(x)); }
// k-pair interleave within 8-blocks: (j, j+4) -> positions (2j, 2j+1)
__device__ __forceinline__ int pig(int k) {
    int j = k & 7;
    return (k & ~7) | ((j < 4) ? (2 * j) : (2 * (j - 4) + 1));
}
__device__ __forceinline__ void cp16(float* s, const float* g) {
    uint32_t sa = (uint32_t)__cvta_generic_to_shared(s);
    asm volatile("cp.async.cg.shared.global [%0], [%1], 16;\n" :: "r"(sa), "l"(g));
}
__device__ __forceinline__ void cp_commit() { asm volatile("cp.async.commit_group;\n"); }
template<int N> __device__ __forceinline__ void cp_wait() {
    asm volatile("cp.async.wait_group %0;\n" :: "n"(N));
}
__device__ __forceinline__ void mma8(float* c, const uint32_t* a, const uint32_t* b) {
    asm volatile(
        "mma.sync.aligned.m16n8k8.row.col.f32.tf32.tf32.f32 "
        "{%0,%1,%2,%3},{%4,%5,%6,%7},{%8,%9},{%0,%1,%2,%3};"
        : "+f"(c[0]), "+f"(c[1]), "+f"(c[2]), "+f"(c[3])
        : "r"(a[0]), "r"(a[1]), "r"(a[2]), "r"(a[3]), "r"(b[0]), "r"(b[1]));
}

// -------- prologue: round+permute embed, Wx, Wo --------------------------
__global__ void prep_k(const float* __restrict__ e, const float* __restrict__ wx,
                       const float* __restrict__ wo) {
    int st = gridDim.x * blockDim.x;
    for (int i = blockIdx.x * blockDim.x + threadIdx.x; i < 1024 * 1024; i += st) {
        int r = i >> 10, k = i & 1023;
        int d = (r << 10) | pig(k);
        g_embr[d] = rndt(e[i]);
        g_Wxr[d]  = rndt(wx[i]);
        g_Wor[d]  = rndt(wo[i]);
    }
}

__global__ void init_k(const float* __restrict__ h0) {
    int i = blockIdx.x * blockDim.x + threadIdx.x;
    if (i < 128) g_flag[i * 32] = 0u;
    for (int j = i; j < Bb * Hh; j += gridDim.x * blockDim.x) {
        int r = j >> 10, k = j & 1023;
        g_h[0][(r << 10) | pig(k)] = rndt(h0[j]);
    }
}

// -------- phase GEMM: C[m][n] = sum_k A[m][k]*W[n][k] + bias[n] ----------
// Tile 128(M) x 128(N) x 32(K), 256 threads = 8 warps (2M x 4N), warp 64x32.
// 4-stage cp.async ring, prefetch depth 3.
#define PS 44
#define TSZ 5632   // 128 rows x 44 per stage (A or B)

__device__ __forceinline__ void stage_p(const float* const* rp, const float* __restrict__ W,
                                        int n0, int k0, float* As, float* Bs, int tid) {
    #pragma unroll
    for (int j = 0; j < 4; j++) {                 // A: 128 rows x 32 floats
        int c = j * 256 + tid; int r = c >> 3, o = c & 7;
        cp16(As + r * PS + o * 4, rp[r] + k0 + o * 4);
    }
    #pragma unroll
    for (int j = 0; j < 4; j++) {                 // B: 128 rows x 32 floats
        int c = j * 256 + tid; int r = c >> 3, o = c & 7;
        cp16(Bs + r * PS + o * 4, W + (size_t)(n0 + r) * 1024 + k0 + o * 4);
    }
}

template<bool GATHER>
__global__ __launch_bounds__(256, 1) void gemm_k(const float* __restrict__ Ab,
                                                 const int* __restrict__ tok,
                                                 const float* __restrict__ W,
                                                 const float* __restrict__ bias,
                                                 float* __restrict__ C) {
    extern __shared__ float sm[];
    float* As = sm;                        // 4 x 5632
    float* Bs = sm + 4 * TSZ;              // 4 x 5632
    const float** rp = (const float**)(sm + 8 * TSZ);   // 128 ptrs

    const int tid = threadIdx.x;
    if (tid < 128) {
        if (GATHER) rp[tid] = Ab + (size_t)tok[tid * Tt + blockIdx.y] * 1024;
        else        rp[tid] = Ab + ((size_t)blockIdx.y * 128 + tid) * 1024;
    }
    __syncthreads();

    const int n0 = blockIdx.x * 128;
    const int lane = tid & 31, w = tid >> 5;
    const int g = lane >> 2, t4 = lane & 3;
    const int wm = (w >> 2) * 64, wn = (w & 3) * 32;

    float acc[4][4][4];
    #pragma unroll
    for (int a = 0; a < 4; a++)
        #pragma unroll
        for (int b = 0; b < 4; b++)
            #pragma unroll
            for (int c = 0; c < 4; c++) acc[a][b][c] = 0.f;

    stage_p(rp, W, n0, 0,  As,           Bs,           tid); cp_commit();
    stage_p(rp, W, n0, 32, As + TSZ,     Bs + TSZ,     tid); cp_commit();
    stage_p(rp, W, n0, 64, As + 2 * TSZ, Bs + 2 * TSZ, tid); cp_commit();

    for (int ks = 0; ks < 32; ks++) {
        if (ks < 30) cp_wait<2>(); else if (ks == 30) cp_wait<1>(); else cp_wait<0>();
        __syncthreads();
        if (ks < 29) {
            int nb = (ks + 3) & 3;
            stage_p(rp, W, n0, (ks + 3) * 32, As + nb * TSZ, Bs + nb * TSZ, tid);
            cp_commit();
        }
        const float* A_ = As + (ks & 3) * TSZ;
        const float* B_ = Bs + (ks & 3) * TSZ;
        #pragma unroll
        for (int kk = 0; kk < 32; kk += 8) {
            uint32_t a[4][4];
            #pragma unroll
            for (int mi = 0; mi < 4; mi++) {
                float2 p0 = *(const float2*)&A_[(wm + mi * 16 + g) * PS + kk + 2 * t4];
                float2 p1 = *(const float2*)&A_[(wm + mi * 16 + 8 + g) * PS + kk + 2 * t4];
                a[mi][0] = __float_as_uint(p0.x); a[mi][1] = __float_as_uint(p1.x);
                a[mi][2] = __float_as_uint(p0.y); a[mi][3] = __float_as_uint(p1.y);
            }
            #pragma unroll
            for (int ni = 0; ni < 4; ni++) {
                float2 q = *(const float2*)&B_[(wn + ni * 8 + g) * PS + kk + 2 * t4];
                uint32_t b[2] = { __float_as_uint(q.x), __float_as_uint(q.y) };
                #pragma unroll
                for (int mi = 0; mi < 4; mi++)
                    mma8(acc[mi][ni], a[mi], b);
            }
        }
    }

    const int m0 = blockIdx.y * 128;
    #pragma unroll
    for (int ni = 0; ni < 4; ni++) {
        int nc = n0 + wn + ni * 8 + 2 * t4;
        float b0 = bias[nc], b1 = bias[nc + 1];
        #pragma unroll
        for (int mi = 0; mi < 4; mi++) {
            int r0 = m0 + wm + mi * 16 + g;
            *(float2*)&C[(size_t)r0 * 1024 + nc] =
                make_float2(acc[mi][ni][0] + b0, acc[mi][ni][1] + b1);
            *(float2*)&C[(size_t)(r0 + 8) * 1024 + nc] =
                make_float2(acc[mi][ni][2] + b0, acc[mi][ni][3] + b1);
        }
    }
}

// -------- persistent recurrence kernel (v7) ------------------------------
// 128 CTAs = 4 independent M-groups x 32 N-CTAs, 256 thr (8 warps).
// Wh in registers; one-shot 4-chunk h staging; partials in own chunk-0.
// NEW: decentralized hand-off. Each CTA publishes its hd columns by
// releasing its OWN flag (named bar over the 128 epilogue threads + tid0
// red.release — no counter contention, earliest possible release). Each
// consumer warp acquire-polls only its 4 producer CTAs (lanes 0-3) before
// staging — per-warp start, group straggler wait diffused.
#define STG 36              // stage row stride (floats)
#define CHB (32 * STG)      // one chunk buffer = 1152 floats
#define CHW (4 * CHB)       // per-warp: 4 buffers = 4608 floats
#define SMEM_RF (8 * CHW)   // 36864 floats = 147456 B

__global__ __launch_bounds__(256, 1) void rnn_k(const float* __restrict__ Wh,
                                                const float* __restrict__ bh,
                                                float* __restrict__ h_e) {
    extern __shared__ float sm[];
    float* Stg = sm;                       // 8 warps x 4 x (32x36)

    const int tid = threadIdx.x;
    const int nq = blockIdx.x & 31, mq = blockIdx.x >> 5;
    const int nb = nq * 32, mb = mq * 32;

    const int lane = tid & 31, w = tid >> 5;
    const int g = lane >> 2, t4 = lane & 3;
    const int kb = w * 128;
    float* SB = Stg + w * CHW;
    const int srow = lane >> 3, su = lane & 7;

    // this warp's 4 producer flags (group mq, producers 4w..4w+3); lane<4 polls
    unsigned int* pflag = &g_flag[((mq << 5) | (4 * w + (lane & 3))) * 32];
    unsigned int* myflag = &g_flag[blockIdx.x * 32];

    // ---- load Wh B-fragments into registers (rounded RNA; once) ----
    uint32_t bfr[4][16][2];
    #pragma unroll
    for (int ni = 0; ni < 4; ni++) {
        const float* Wrow = Wh + (size_t)(nb + ni * 8 + g) * 1024 + kb + t4;
        #pragma unroll
        for (int kf = 0; kf < 16; kf++) {
            bfr[ni][kf][0] = f2t(Wrow[kf * 8]);
            bfr[ni][kf][1] = f2t(Wrow[kf * 8 + 4]);
        }
    }

    // epilogue mapping (tid<128): row er, cols [gcb, gcb+8)
    const int er = tid & 31, eblk = tid >> 5;
    const int gr = mb + er, gcb = nb + eblk * 8;
    float bhv[8];
    float4 xq0, xq1;
    if (tid < 128) {
        float4 q0 = *(const float4*)&bh[gcb];
        float4 q1 = *(const float4*)&bh[gcb + 4];
        bhv[0]=q0.x; bhv[1]=q0.y; bhv[2]=q0.z; bhv[3]=q0.w;
        bhv[4]=q1.x; bhv[5]=q1.y; bhv[6]=q1.z; bhv[7]=q1.w;
        xq0 = *(const float4*)&g_xp[(size_t)gr * 1024 + gcb];
        xq1 = *(const float4*)&g_xp[(size_t)gr * 1024 + gcb + 4];
    }
    __syncthreads();

    for (int t = 0; t < Tt; t++) {
        const float* hs = g_h[t & 1];
        float* hd = g_h[(t + 1) & 1];
        const float* gsrc = hs + (size_t)mb * 1024 + kb;

        // acquire this warp's 4 producers (flag >= t means h(t) published)
        if (t > 0 && lane < 4) {
            unsigned tgt = (unsigned)t, vv;
            do {
                asm volatile("ld.acquire.gpu.u32 %0, [%1];" : "=r"(vv) : "l"(pflag));
            } while (vv < tgt);
        }
        __syncwarp();

        float acc[2][4][4];
        #pragma unroll
        for (int a = 0; a < 2; a++)
            #pragma unroll
            for (int b = 0; b < 4; b++)
                #pragma unroll
                for (int c = 0; c < 4; c++) acc[a][b][c] = 0.f;

        // stage ALL 4 chunks now (one L2 round trip, 4 commit groups)
        #pragma unroll
        for (int cc = 0; cc < 4; cc++) {
            #pragma unroll
            for (int j = 0; j < 8; j++) {
                int r = srow + 4 * j;
                cp16(SB + cc * CHB + r * STG + su * 4,
                     gsrc + (size_t)r * 1024 + cc * 32 + su * 4);
            }
            cp_commit();
        }

        #pragma unroll
        for (int c = 0; c < 4; c++) {
            if (c == 0) cp_wait<3>();
            else if (c == 1) cp_wait<2>();
            else if (c == 2) cp_wait<1>();
            else cp_wait<0>();
            __syncwarp();
            const float* B_ = SB + c * CHB;
            #pragma unroll
            for (int kf = 0; kf < 4; kf++) {
                uint32_t a[2][4];
                #pragma unroll
                for (int mi = 0; mi < 2; mi++) {
                    float2 p0 = *(const float2*)&B_[(mi * 16 + g) * STG + kf * 8 + 2 * t4];
                    float2 p1 = *(const float2*)&B_[(mi * 16 + 8 + g) * STG + kf * 8 + 2 * t4];
                    a[mi][0] = __float_as_uint(p0.x); a[mi][1] = __float_as_uint(p1.x);
                    a[mi][2] = __float_as_uint(p0.y); a[mi][3] = __float_as_uint(p1.y);
                }
                #pragma unroll
                for (int ni = 0; ni < 4; ni++) {
                    mma8(acc[0][ni], a[0], bfr[ni][c * 4 + kf]);
                    mma8(acc[1][ni], a[1], bfr[ni][c * 4 + kf]);
                }
            }
        }

        // K-partials into own chunk-0 buffer (first consumed; warp-private)
        #pragma unroll
        for (int mi = 0; mi < 2; mi++)
            #pragma unroll
            for (int ni = 0; ni < 4; ni++) {
                int nc = ni * 8 + 2 * t4;
                *(float2*)&SB[(mi * 16 + g) * STG + nc] =
                    make_float2(acc[mi][ni][0], acc[mi][ni][1]);
                *(float2*)&SB[(mi * 16 + 8 + g) * STG + nc] =
                    make_float2(acc[mi][ni][2], acc[mi][ni][3]);
            }
        __syncthreads();   // (A) partials visible to reducing warps

        // reduce 8 partials + tanh; store NEXT-STATE hd; publish own flag
        float v[8], r[8];
        if (tid < 128) {
            float s[8] = {0.f,0.f,0.f,0.f,0.f,0.f,0.f,0.f};
            #pragma unroll
            for (int ww = 0; ww < 8; ww++) {
                const float* Rr = Stg + ww * CHW + er * STG + eblk * 8;
                float4 r0 = *(const float4*)&Rr[0];
                float4 r1 = *(const float4*)&Rr[4];
                s[0] += r0.x; s[1] += r0.y; s[2] += r0.z; s[3] += r0.w;
                s[4] += r1.x; s[5] += r1.y; s[6] += r1.z; s[7] += r1.w;
            }
            v[0] = tanhf(s[0] + xq0.x + bhv[0]);
            v[1] = tanhf(s[1] + xq0.y + bhv[1]);
            v[2] = tanhf(s[2] + xq0.z + bhv[2]);
            v[3] = tanhf(s[3] + xq0.w + bhv[3]);
            v[4] = tanhf(s[4] + xq1.x + bhv[4]);
            v[5] = tanhf(s[5] + xq1.y + bhv[5]);
            v[6] = tanhf(s[6] + xq1.z + bhv[6]);
            v[7] = tanhf(s[7] + xq1.w + bhv[7]);
            #pragma unroll
            for (int j = 0; j < 8; j++) r[j] = rndt(v[j]);
            *(float4*)&hd[(size_t)gr * 1024 + gcb]     = make_float4(r[0], r[4], r[1], r[5]);
            *(float4*)&hd[(size_t)gr * 1024 + gcb + 4] = make_float4(r[2], r[6], r[3], r[7]);

            // named barrier over the 128 storing threads, then release own flag
            asm volatile("bar.sync 1, 128;" ::: "memory");
            if (tid == 0)
                asm volatile("red.release.gpu.global.add.u32 [%0], %1;"
                             :: "l"(myflag), "r"(1u) : "memory");

            // stores nobody consumes this step + next xp prefetch
            size_t orow = ((size_t)gr * Tt + t) * 1024 + gcb;
            *(float4*)&h_e[orow]     = make_float4(v[0], v[1], v[2], v[3]);
            *(float4*)&h_e[orow + 4] = make_float4(v[4], v[5], v[6], v[7]);
            *(float4*)&g_hr[orow]     = make_float4(r[0], r[4], r[1], r[5]);
            *(float4*)&g_hr[orow + 4] = make_float4(r[2], r[6], r[3], r[7]);
            if (t + 1 < Tt) {
                xq0 = *(const float4*)&g_xp[(size_t)((t + 1) * 128 + gr) * 1024 + gcb];
                xq1 = *(const float4*)&g_xp[(size_t)((t + 1) * 128 + gr) * 1024 + gcb + 4];
            }
        }
        __syncthreads();   // (B) reduce reads done -> chunk buffers reusable
    }
}

// -------- launch ---------------------------------------------------------
extern "C" void kernel_launch(void* const* d_in, const int* in_sizes, int n_in,
                              void* d_out, int out_size) {
    (void)in_sizes; (void)n_in; (void)out_size;
    const int*   x      = (const int*)d_in[0];
    const float* h_init = (const float*)d_in[1];
    const float* embed  = (const float*)d_in[2];
    const float* Wx     = (const float*)d_in[3];
    const float* bx     = (const float*)d_in[4];
    const float* Wh     = (const float*)d_in[5];
    const float* bh     = (const float*)d_in[6];
    const float* Wo     = (const float*)d_in[7];
    const float* bo     = (const float*)d_in[8];

    float* out = (float*)d_out;
    float* h_e = out;                       // [B][T][H]
    float* y_e = out + (size_t)BT * Hh;     // [B][T][V]

    const int SMEM_P = 8 * TSZ * 4 + 128 * 8;               // 180224 + 1024 = 181248
    const int SMEM_R = SMEM_RF * 4;                         // 147456

    cudaFuncSetAttribute(gemm_k<true>,  cudaFuncAttributeMaxDynamicSharedMemorySize, SMEM_P);
    cudaFuncSetAttribute(gemm_k<false>, cudaFuncAttributeMaxDynamicSharedMemorySize, SMEM_P);
    cudaFuncSetAttribute(rnn_k,         cudaFuncAttributeMaxDynamicSharedMemorySize, SMEM_R);

    void* xp_ptr = nullptr;   cudaGetSymbolAddress(&xp_ptr, g_xp);
    void* hr_ptr = nullptr;   cudaGetSymbolAddress(&hr_ptr, g_hr);
    void* emb_ptr = nullptr;  cudaGetSymbolAddress(&emb_ptr, g_embr);
    void* wx_ptr = nullptr;   cudaGetSymbolAddress(&wx_ptr, g_Wxr);
    void* wo_ptr = nullptr;   cudaGetSymbolAddress(&wo_ptr, g_Wor);

    // 1. round+permute embed/Wx/Wo; reset flags; h_init -> g_h[0]
    prep_k<<<512, 256>>>(embed, Wx, Wo);
    init_k<<<128, 256>>>(h_init);
    // 2. xp[t][b][:] = embed_r[x[b][t]] @ Wx_r^T + bx
    gemm_k<true><<<dim3(8, 512), 256, SMEM_P>>>((const float*)emb_ptr, x,
                                                (const float*)wx_ptr, bx, (float*)xp_ptr);
    // 3. serial recurrence -> h_e (+ rounded copies)
    rnn_k<<<128, 256, SMEM_R>>>(Wh, bh, h_e);
    // 4. y = h_r @ Wo_r^T + bo
    gemm_k<false><<<dim3(8, 512), 256, SMEM_P>>>((const float*)hr_ptr, nullptr,
                                                 (const float*)wo_ptr, bo, y_e);
}